// round 8
// baseline (speedup 1.0000x reference)
#include <cuda_runtime.h>
#include <math_constants.h>

#define NPTS  16384
#define KNN   10
#define NL    11                 // K+1 slots per list (self may occupy one)
#define CH    2048               // candidates per chunk (smem tile 32KB)
#define NCH   (NPTS / CH)        // 8 chunks total
#define NCHA  2                  // phase-A chunks (unseeded fill)
#define NCHB  (NCH - NCHA)       // 6 phase-B chunks (seeded)
#define QPB   128                // threads (queries) per block
#define UNR   8                  // candidates staged per group

// (-2x, -2y, -2z, x^2+y^2+z^2) per point
__device__ float4 g_pos4[NPTS];
// accumulators: 0 sparsity Σ|op|, 1 opacity Σ(op-.5)^2, 2 scale Σ|s-1|, 3 smooth Σ|Δop|
__device__ float g_acc[4];
// per-query, per-chunk candidate lists
__device__ float g_nd[NPTS][NCH][NL];
__device__ int   g_ni[NPTS][NCH][NL];

__device__ __forceinline__ float warp_sum(float v) {
#pragma unroll
    for (int o = 16; o; o >>= 1) v += __shfl_xor_sync(0xffffffffu, v, o);
    return v;
}

__global__ void init_kernel() {
    if (threadIdx.x < 4) g_acc[threadIdx.x] = 0.0f;
}

__global__ void prep_kernel(const float* __restrict__ pos,
                            const float* __restrict__ op,
                            const float* __restrict__ sc) {
    int i = blockIdx.x * blockDim.x + threadIdx.x;   // grid covers exactly NPTS
    float x = pos[3 * i + 0], y = pos[3 * i + 1], z = pos[3 * i + 2];
    float sq = fmaf(z, z, fmaf(y, y, x * x));
    g_pos4[i] = make_float4(-2.0f * x, -2.0f * y, -2.0f * z, sq);

    float o  = op[i];
    float sp = fabsf(o);
    float ol = (o - 0.5f) * (o - 0.5f);
    float sl = fabsf(sc[3 * i + 0] - 1.0f)
             + fabsf(sc[3 * i + 1] - 1.0f)
             + fabsf(sc[3 * i + 2] - 1.0f);
    sp = warp_sum(sp);
    ol = warp_sum(ol);
    sl = warp_sum(sl);
    if ((threadIdx.x & 31) == 0) {
        atomicAdd(&g_acc[0], sp);
        atomicAdd(&g_acc[1], ol);
        atomicAdd(&g_acc[2], sl);
    }
}

// branchless sorted insert: 11 independent compares + select cascade (no BSSY)
__device__ __forceinline__ void insert_branchless(float d, int id,
                                                  float bd[NL], int bi[NL]) {
    bool lt[NL];
#pragma unroll
    for (int k = 0; k < NL; k++) lt[k] = d < bd[k];
#pragma unroll
    for (int k = NL - 1; k > 0; --k) {
        bd[k] = lt[k - 1] ? bd[k - 1] : (lt[k] ? d : bd[k]);
        bi[k] = lt[k - 1] ? bi[k - 1] : (lt[k] ? id : bi[k]);
    }
    bd[0] = lt[0] ? d : bd[0];
    bi[0] = lt[0] ? id : bi[0];
}

// scan one staged chunk; ballot-gated (warp-uniform branch, no divergence region)
__device__ __forceinline__ void scan_chunk(const float4* __restrict__ tile, int gbase,
                                           float qx, float qy, float qz, float qsq,
                                           float bd[NL], int bi[NL]) {
    for (int c = 0; c < CH; c += UNR) {
        float d2[UNR];
#pragma unroll
        for (int u = 0; u < UNR; u++) {
            float4 p = tile[c + u];   // broadcast: all lanes same address
            d2[u] = qsq + fmaf(p.x, qx, fmaf(p.y, qy, fmaf(p.z, qz, p.w)));
        }
#pragma unroll
        for (int u = 0; u < UNR; u++) {
            unsigned m = __ballot_sync(0xffffffffu, d2[u] < bd[NL - 1]);
            if (m)   // warp-uniform branch
                insert_branchless(d2[u], gbase + c + u, bd, bi);
        }
    }
}

// Phase A: unseeded exact top-11 over chunks 0..NCHA-1.
// grid = (NPTS/QPB) * NCHA = 256 blocks of 128 threads.
__global__ void __launch_bounds__(QPB) knnA_kernel(const float* __restrict__ pos) {
    __shared__ float4 tile[CH];
    const int chunk = blockIdx.x & (NCHA - 1);
    const int q     = (blockIdx.x >> 1) * QPB + threadIdx.x;

    const float qx = pos[3 * q + 0], qy = pos[3 * q + 1], qz = pos[3 * q + 2];
    const float qsq = fmaf(qz, qz, fmaf(qy, qy, qx * qx));

    float bd[NL]; int bi[NL];
#pragma unroll
    for (int k = 0; k < NL; k++) { bd[k] = CUDART_INF_F; bi[k] = -1; }

    const int base = chunk * CH;
#pragma unroll
    for (int r = 0; r < CH / QPB; r++)
        tile[r * QPB + threadIdx.x] = g_pos4[base + r * QPB + threadIdx.x];
    __syncthreads();

    scan_chunk(tile, base, qx, qy, qz, qsq, bd, bi);

#pragma unroll
    for (int k = 0; k < NL; k++) {
        g_nd[q][chunk][k] = bd[k];
        g_ni[q][chunk][k] = bi[k];
    }
}

// Phase B: seeded scan of chunks NCHA..NCH-1; list initialized to the seed
// threshold (min of phase-A 11th-best), which is >= the global 11th-best, so
// every global top-11 member still inserts. grid = (NPTS/QPB)*NCHB = 768 blocks.
__global__ void __launch_bounds__(QPB) knnB_kernel(const float* __restrict__ pos) {
    __shared__ float4 tile[CH];
    const int chunk = NCHA + (int)(blockIdx.x % NCHB);
    const int q     = (int)(blockIdx.x / NCHB) * QPB + threadIdx.x;

    const float qx = pos[3 * q + 0], qy = pos[3 * q + 1], qz = pos[3 * q + 2];
    const float qsq = fmaf(qz, qz, fmaf(qy, qy, qx * qx));

    const float seed = fminf(g_nd[q][0][NL - 1], g_nd[q][1][NL - 1]);

    float bd[NL]; int bi[NL];
#pragma unroll
    for (int k = 0; k < NL; k++) { bd[k] = seed; bi[k] = -1; }

    const int base = chunk * CH;
#pragma unroll
    for (int r = 0; r < CH / QPB; r++)
        tile[r * QPB + threadIdx.x] = g_pos4[base + r * QPB + threadIdx.x];
    __syncthreads();

    scan_chunk(tile, base, qx, qy, qz, qsq, bd, bi);

#pragma unroll
    for (int k = 0; k < NL; k++) {
        g_nd[q][chunk][k] = bd[k];
        g_ni[q][chunk][k] = bi[k];
    }
}

// merge all NCH lists per query (filtering self/invalid), accumulate smoothness
__global__ void merge_kernel(const float* __restrict__ op) {
    int q = blockIdx.x * blockDim.x + threadIdx.x;

    float bd[NL]; int bi[NL];
#pragma unroll
    for (int k = 0; k < NL; k++) { bd[k] = CUDART_INF_F; bi[k] = -1; }

#pragma unroll
    for (int c = 0; c < NCH; c++) {
#pragma unroll
        for (int e = 0; e < NL; e++) {
            float d = g_nd[q][c][e];
            int   j = g_ni[q][c][e];
            // invalid (j<0) or self (j==q) -> never inserts
            if (j < 0 || j == q) d = CUDART_INF_F;
            insert_branchless(d, j, bd, bi);
        }
    }

    float oq = op[q];
    float s = 0.0f;
#pragma unroll
    for (int k = 0; k < KNN; k++)
        s += fabsf(oq - op[bi[k]]);

    s = warp_sum(s);
    if ((threadIdx.x & 31) == 0) atomicAdd(&g_acc[3], s);
}

__global__ void final_kernel(float* __restrict__ out) {
    float sparsity  = g_acc[0] * (1.0f / NPTS);
    float opacity   = g_acc[1] * (1.0f / NPTS);
    float scale     = g_acc[2] * (1.0f / (3.0f * NPTS));
    float smooth    = g_acc[3] * (1.0f / ((float)NPTS * KNN));
    out[0] = 0.01f * sparsity + 0.1f * smooth + scale + opacity;
}

extern "C" void kernel_launch(void* const* d_in, const int* in_sizes, int n_in,
                              void* d_out, int out_size) {
    const float* pos = (const float*)d_in[0];
    const float* op  = (const float*)d_in[1];
    const float* sc  = (const float*)d_in[2];
    float* out = (float*)d_out;

    init_kernel<<<1, 32>>>();
    prep_kernel<<<NPTS / 256, 256>>>(pos, op, sc);
    knnA_kernel<<<(NPTS / QPB) * NCHA, QPB>>>(pos);
    knnB_kernel<<<(NPTS / QPB) * NCHB, QPB>>>(pos);
    merge_kernel<<<NPTS / 256, 256>>>(op);
    final_kernel<<<1, 1>>>(out);
}

// round 9
// speedup vs baseline: 1.5409x; 1.5409x over previous
#include <cuda_runtime.h>
#include <math_constants.h>

#define NPTS  16384
#define KNN   10
#define NL    11                 // K+1 slots per list (self may occupy one)
#define CH    2048               // candidates per chunk (smem tile 32KB)
#define NCH   (NPTS / CH)        // 8 chunks total
#define NCHA  2                  // phase-A chunks (unseeded fill)
#define NCHB  (NCH - NCHA)       // 6 phase-B chunks (seeded)
#define QPB   128                // threads (queries) per block
#define UNR   8                  // candidates per gated group

// (-2x, -2y, -2z, x^2+y^2+z^2) per point
__device__ float4 g_pos4[NPTS];
// accumulators: 0 sparsity Σ|op|, 1 opacity Σ(op-.5)^2, 2 scale Σ|s-1|, 3 smooth Σ|Δop|
__device__ float g_acc[4];
// per-query, per-chunk candidate lists (t-space values: d2 - qsq, monotone per query)
__device__ float g_nd[NPTS][NCH][NL];
__device__ int   g_ni[NPTS][NCH][NL];

__device__ __forceinline__ float warp_sum(float v) {
#pragma unroll
    for (int o = 16; o; o >>= 1) v += __shfl_xor_sync(0xffffffffu, v, o);
    return v;
}

__global__ void init_kernel() {
    if (threadIdx.x < 4) g_acc[threadIdx.x] = 0.0f;
}

__global__ void prep_kernel(const float* __restrict__ pos,
                            const float* __restrict__ op,
                            const float* __restrict__ sc) {
    int i = blockIdx.x * blockDim.x + threadIdx.x;   // grid covers exactly NPTS
    float x = pos[3 * i + 0], y = pos[3 * i + 1], z = pos[3 * i + 2];
    float sq = fmaf(z, z, fmaf(y, y, x * x));
    g_pos4[i] = make_float4(-2.0f * x, -2.0f * y, -2.0f * z, sq);

    float o  = op[i];
    float sp = fabsf(o);
    float ol = (o - 0.5f) * (o - 0.5f);
    float sl = fabsf(sc[3 * i + 0] - 1.0f)
             + fabsf(sc[3 * i + 1] - 1.0f)
             + fabsf(sc[3 * i + 2] - 1.0f);
    sp = warp_sum(sp);
    ol = warp_sum(ol);
    sl = warp_sum(sl);
    if ((threadIdx.x & 31) == 0) {
        atomicAdd(&g_acc[0], sp);
        atomicAdd(&g_acc[1], ol);
        atomicAdd(&g_acc[2], sl);
    }
}

// branchless sorted insert: compares + select cascade (no inner branches)
__device__ __forceinline__ void insert_branchless(float d, int id,
                                                  float bd[NL], int bi[NL]) {
    bool lt[NL];
#pragma unroll
    for (int k = 0; k < NL; k++) lt[k] = d < bd[k];
#pragma unroll
    for (int k = NL - 1; k > 0; --k) {
        bd[k] = lt[k - 1] ? bd[k - 1] : (lt[k] ? d : bd[k]);
        bi[k] = lt[k - 1] ? bi[k - 1] : (lt[k] ? id : bi[k]);
    }
    bd[0] = lt[0] ? d : bd[0];
    bi[0] = lt[0] ? id : bi[0];
}

// scan one staged chunk: 8-wide min-tree group gate, inner ballot gates,
// branchless insert. thr mirrors bd[NL-1].
__device__ __forceinline__ void scan_chunk(const float4* __restrict__ tile, int gbase,
                                           float qx, float qy, float qz,
                                           float bd[NL], int bi[NL]) {
    float thr = bd[NL - 1];
    for (int c = 0; c < CH; c += UNR) {
        float d2[UNR];
#pragma unroll
        for (int u = 0; u < UNR; u++) {
            float4 p = tile[c + u];   // broadcast: all lanes same address
            d2[u] = fmaf(p.x, qx, fmaf(p.y, qy, fmaf(p.z, qz, p.w)));  // t-space
        }
        // group min-tree: one gate per 8 candidates
        float m0 = fminf(d2[0], d2[1]);
        float m1 = fminf(d2[2], d2[3]);
        float m2 = fminf(d2[4], d2[5]);
        float m3 = fminf(d2[6], d2[7]);
        float m  = fminf(fminf(m0, m1), fminf(m2, m3));
        if (__ballot_sync(0xffffffffu, m < thr)) {  // warp-uniform branch
#pragma unroll
            for (int u = 0; u < UNR; u++) {
                if (__ballot_sync(0xffffffffu, d2[u] < thr)) {
                    insert_branchless(d2[u], gbase + c + u, bd, bi);
                    thr = bd[NL - 1];
                }
            }
        }
    }
}

// Phase A: unseeded exact top-11 over chunks 0..NCHA-1.
// grid = (NPTS/QPB) * NCHA = 256 blocks of 128 threads.
__global__ void __launch_bounds__(QPB) knnA_kernel(const float* __restrict__ pos) {
    __shared__ float4 tile[CH];
    const int chunk = blockIdx.x & (NCHA - 1);
    const int q     = (blockIdx.x >> 1) * QPB + threadIdx.x;

    const float qx = pos[3 * q + 0], qy = pos[3 * q + 1], qz = pos[3 * q + 2];

    float bd[NL]; int bi[NL];
#pragma unroll
    for (int k = 0; k < NL; k++) { bd[k] = CUDART_INF_F; bi[k] = -1; }

    const int base = chunk * CH;
#pragma unroll
    for (int r = 0; r < CH / QPB; r++)
        tile[r * QPB + threadIdx.x] = g_pos4[base + r * QPB + threadIdx.x];
    __syncthreads();

    scan_chunk(tile, base, qx, qy, qz, bd, bi);

#pragma unroll
    for (int k = 0; k < NL; k++) {
        g_nd[q][chunk][k] = bd[k];
        g_ni[q][chunk][k] = bi[k];
    }
}

// Phase B: seeded scan of chunks NCHA..NCH-1. Seed = min of phase-A 11th-best
// (t-space), an upper bound on the global 11th, so every global top-11 member
// still inserts. grid = (NPTS/QPB)*NCHB = 768 blocks.
__global__ void __launch_bounds__(QPB) knnB_kernel(const float* __restrict__ pos) {
    __shared__ float4 tile[CH];
    const int chunk = NCHA + (int)(blockIdx.x % NCHB);
    const int q     = (int)(blockIdx.x / NCHB) * QPB + threadIdx.x;

    const float qx = pos[3 * q + 0], qy = pos[3 * q + 1], qz = pos[3 * q + 2];

    const float seed = fminf(g_nd[q][0][NL - 1], g_nd[q][1][NL - 1]);

    float bd[NL]; int bi[NL];
#pragma unroll
    for (int k = 0; k < NL; k++) { bd[k] = seed; bi[k] = -1; }

    const int base = chunk * CH;
#pragma unroll
    for (int r = 0; r < CH / QPB; r++)
        tile[r * QPB + threadIdx.x] = g_pos4[base + r * QPB + threadIdx.x];
    __syncthreads();

    scan_chunk(tile, base, qx, qy, qz, bd, bi);

#pragma unroll
    for (int k = 0; k < NL; k++) {
        g_nd[q][chunk][k] = bd[k];
        g_ni[q][chunk][k] = bi[k];
    }
}

// merge all NCH lists per query (filtering self/invalid), accumulate smoothness
__global__ void merge_kernel(const float* __restrict__ op) {
    int q = blockIdx.x * blockDim.x + threadIdx.x;

    float bd[NL]; int bi[NL];
#pragma unroll
    for (int k = 0; k < NL; k++) { bd[k] = CUDART_INF_F; bi[k] = -1; }

#pragma unroll
    for (int c = 0; c < NCH; c++) {
#pragma unroll
        for (int e = 0; e < NL; e++) {
            float d = g_nd[q][c][e];
            int   j = g_ni[q][c][e];
            // invalid (j<0) or self (j==q) -> never inserts
            if (j < 0 || j == q) d = CUDART_INF_F;
            insert_branchless(d, j, bd, bi);
        }
    }

    float oq = op[q];
    float s = 0.0f;
#pragma unroll
    for (int k = 0; k < KNN; k++)
        s += fabsf(oq - op[bi[k]]);

    s = warp_sum(s);
    if ((threadIdx.x & 31) == 0) atomicAdd(&g_acc[3], s);
}

__global__ void final_kernel(float* __restrict__ out) {
    float sparsity  = g_acc[0] * (1.0f / NPTS);
    float opacity   = g_acc[1] * (1.0f / NPTS);
    float scale     = g_acc[2] * (1.0f / (3.0f * NPTS));
    float smooth    = g_acc[3] * (1.0f / ((float)NPTS * KNN));
    out[0] = 0.01f * sparsity + 0.1f * smooth + scale + opacity;
}

extern "C" void kernel_launch(void* const* d_in, const int* in_sizes, int n_in,
                              void* d_out, int out_size) {
    const float* pos = (const float*)d_in[0];
    const float* op  = (const float*)d_in[1];
    const float* sc  = (const float*)d_in[2];
    float* out = (float*)d_out;

    init_kernel<<<1, 32>>>();
    prep_kernel<<<NPTS / 256, 256>>>(pos, op, sc);
    knnA_kernel<<<(NPTS / QPB) * NCHA, QPB>>>(pos);
    knnB_kernel<<<(NPTS / QPB) * NCHB, QPB>>>(pos);
    merge_kernel<<<NPTS / 256, 256>>>(op);
    final_kernel<<<1, 1>>>(out);
}

// round 10
// speedup vs baseline: 1.7697x; 1.1484x over previous
#include <cuda_runtime.h>
#include <math_constants.h>

#define NPTS  16384
#define KNN   10
#define NL    11                 // K+1 slots per list (self may occupy one)
#define CH    1024               // candidates per chunk
#define NCH   16                 // chunk 0 = bootstrap, 1..15 = phase B
#define NCHB  (NCH - 1)
#define QPB   128                // threads (queries) per block
#define S1    320                // bootstrap stage-1 length (always-insert)
#define CAPS  48                 // bootstrap quad-buffer capacity
#define CAPB  32                 // phase-B quad-buffer capacity

// (-2x, -2y, -2z, x^2+y^2+z^2) per point
__device__ float4 g_pos4[NPTS];
// accumulators: 0 sparsity Σ|op|, 1 opacity Σ(op-.5)^2, 2 scale Σ|s-1|, 3 smooth Σ|Δop|
__device__ float g_acc[4];
// per-chunk candidate lists, t-space; [chunk][slot][q] for coalesced access
__device__ float g_nd[NCH][NL][NPTS];
__device__ int   g_ni[NCH][NL][NPTS];

__device__ __forceinline__ float warp_sum(float v) {
#pragma unroll
    for (int o = 16; o; o >>= 1) v += __shfl_xor_sync(0xffffffffu, v, o);
    return v;
}

__global__ void init_kernel() {
    if (threadIdx.x < 4) g_acc[threadIdx.x] = 0.0f;
}

__global__ void prep_kernel(const float* __restrict__ pos,
                            const float* __restrict__ op,
                            const float* __restrict__ sc) {
    int i = blockIdx.x * blockDim.x + threadIdx.x;   // grid covers exactly NPTS
    float x = pos[3 * i + 0], y = pos[3 * i + 1], z = pos[3 * i + 2];
    float sq = fmaf(z, z, fmaf(y, y, x * x));
    g_pos4[i] = make_float4(-2.0f * x, -2.0f * y, -2.0f * z, sq);

    float o  = op[i];
    float sp = fabsf(o);
    float ol = (o - 0.5f) * (o - 0.5f);
    float sl = fabsf(sc[3 * i + 0] - 1.0f)
             + fabsf(sc[3 * i + 1] - 1.0f)
             + fabsf(sc[3 * i + 2] - 1.0f);
    sp = warp_sum(sp);
    ol = warp_sum(ol);
    sl = warp_sum(sl);
    if ((threadIdx.x & 31) == 0) {
        atomicAdd(&g_acc[0], sp);
        atomicAdd(&g_acc[1], ol);
        atomicAdd(&g_acc[2], sl);
    }
}

// branchless sorted insert: compares + select cascade (no inner branches)
__device__ __forceinline__ void insert_branchless(float d, int id,
                                                  float bd[NL], int bi[NL]) {
    bool lt[NL];
#pragma unroll
    for (int k = 0; k < NL; k++) lt[k] = d < bd[k];
#pragma unroll
    for (int k = NL - 1; k > 0; --k) {
        bd[k] = lt[k - 1] ? bd[k - 1] : (lt[k] ? d : bd[k]);
        bi[k] = lt[k - 1] ? bi[k - 1] : (lt[k] ? id : bi[k]);
    }
    bd[0] = lt[0] ? d : bd[0];
    bi[0] = lt[0] ? id : bi[0];
}

__device__ __forceinline__ float tval(float4 p, float qx, float qy, float qz) {
    return fmaf(p.x, qx, fmaf(p.y, qy, fmaf(p.z, qz, p.w)));  // d2 - qsq (monotone)
}

// Bootstrap: exact top-11 of chunk 0 (candidates 0..1023) per query.
// Stage 1: always-insert first S1 -> threshold. Stage 2: quad-buffered remainder.
__global__ void __launch_bounds__(QPB) boot_kernel(const float* __restrict__ pos) {
    __shared__ float4 tile[CH];               // 16KB
    __shared__ int    buf[QPB][CAPS + 1];     // 24.5KB (+1 trash slot)

    const int q = blockIdx.x * QPB + threadIdx.x;
    const float qx = pos[3 * q + 0], qy = pos[3 * q + 1], qz = pos[3 * q + 2];

#pragma unroll
    for (int r = 0; r < CH / QPB; r++)
        tile[r * QPB + threadIdx.x] = g_pos4[r * QPB + threadIdx.x];
    __syncthreads();

    float bd[NL]; int bi[NL];
#pragma unroll
    for (int k = 0; k < NL; k++) { bd[k] = CUDART_INF_F; bi[k] = -1; }

    // stage 1: unconditional insert (no divergence at all)
#pragma unroll 1
    for (int c = 0; c < S1; c++)
        insert_branchless(tval(tile[c], qx, qy, qz), c, bd, bi);

    const float thr = bd[NL - 1];
    int* sbuf = buf[threadIdx.x];
    int cnt = 0;

    // stage 2: predicated quad buffering (no branches, no ballots)
#pragma unroll 2
    for (int c = S1; c < CH; c += 4) {
        float t0 = tval(tile[c + 0], qx, qy, qz);
        float t1 = tval(tile[c + 1], qx, qy, qz);
        float t2 = tval(tile[c + 2], qx, qy, qz);
        float t3 = tval(tile[c + 3], qx, qy, qz);
        float m  = fminf(fminf(t0, t1), fminf(t2, t3));
        bool pass = m < thr;
        sbuf[pass ? cnt : CAPS] = c;   // SEL + STS, trash slot when !pass
        cnt += (int)pass;
    }

    if (cnt > CAPS) {
        // overflow fallback (astronomically rare): exact rescan
#pragma unroll 1
        for (int c = S1; c < CH; c++) {
            float t = tval(tile[c], qx, qy, qz);
            if (t < bd[NL - 1]) insert_branchless(t, c, bd, bi);
        }
    } else {
#pragma unroll 1
        for (int e = 0; e < cnt; e++) {
            int cb = sbuf[e] & (CH - 4);
#pragma unroll
            for (int u = 0; u < 4; u++) {
                float t = tval(tile[cb + u], qx, qy, qz);
                if (t < bd[NL - 1]) insert_branchless(t, cb + u, bd, bi);
            }
        }
    }

#pragma unroll
    for (int k = 0; k < NL; k++) {
        g_nd[0][k][q] = bd[k];
        g_ni[0][k][q] = bi[k];
    }
}

// Phase B: chunks 1..15, seeded by chunk-0's 11th (t-space upper bound on the
// global 11th -> exact). Fully predicated quad-buffered scan: zero warp-level
// amplification. grid = (NPTS/QPB)*NCHB = 1920 blocks of 128.
__global__ void __launch_bounds__(QPB) knnb_kernel(const float* __restrict__ pos) {
    __shared__ float4 tile[CH];               // 16KB
    __shared__ int    buf[QPB][CAPB + 1];     // 16.5KB

    const int chunk = 1 + (int)(blockIdx.x % NCHB);
    const int q     = (int)(blockIdx.x / NCHB) * QPB + threadIdx.x;
    const float qx = pos[3 * q + 0], qy = pos[3 * q + 1], qz = pos[3 * q + 2];

    const int base = chunk * CH;
#pragma unroll
    for (int r = 0; r < CH / QPB; r++)
        tile[r * QPB + threadIdx.x] = g_pos4[base + r * QPB + threadIdx.x];
    __syncthreads();

    const float seed = g_nd[0][NL - 1][q];   // coalesced
    const float thr  = seed;
    int* sbuf = buf[threadIdx.x];
    int cnt = 0;

#pragma unroll 2
    for (int c = 0; c < CH; c += 4) {
        float t0 = tval(tile[c + 0], qx, qy, qz);
        float t1 = tval(tile[c + 1], qx, qy, qz);
        float t2 = tval(tile[c + 2], qx, qy, qz);
        float t3 = tval(tile[c + 3], qx, qy, qz);
        float m  = fminf(fminf(t0, t1), fminf(t2, t3));
        bool pass = m < thr;
        sbuf[pass ? cnt : CAPB] = c;
        cnt += (int)pass;
    }

    // build per-chunk top-11 (seed-initialized; padding idx=-1 filtered in merge)
    float bd[NL]; int bi[NL];
#pragma unroll
    for (int k = 0; k < NL; k++) { bd[k] = seed; bi[k] = -1; }

    if (cnt > CAPB) {
        // overflow fallback (rare): exact rescan under seed
#pragma unroll 1
        for (int c = 0; c < CH; c++) {
            float t = tval(tile[c], qx, qy, qz);
            if (t < bd[NL - 1]) insert_branchless(t, base + c, bd, bi);
        }
    } else {
#pragma unroll 1
        for (int e = 0; e < cnt; e++) {
            int cb = sbuf[e] & (CH - 4);
#pragma unroll
            for (int u = 0; u < 4; u++) {
                float t = tval(tile[cb + u], qx, qy, qz);
                if (t < bd[NL - 1]) insert_branchless(t, base + cb + u, bd, bi);
            }
        }
    }

#pragma unroll
    for (int k = 0; k < NL; k++) {
        g_nd[chunk][k][q] = bd[k];
        g_ni[chunk][k][q] = bi[k];
    }
}

// merge all NCH lists per query (filtering self/invalid), accumulate smoothness
__global__ void merge_kernel(const float* __restrict__ op) {
    int q = blockIdx.x * blockDim.x + threadIdx.x;

    float bd[NL]; int bi[NL];
#pragma unroll
    for (int k = 0; k < NL; k++) { bd[k] = CUDART_INF_F; bi[k] = -1; }

#pragma unroll 1
    for (int c = 0; c < NCH; c++) {
#pragma unroll 1
        for (int e = 0; e < NL; e++) {
            float d = g_nd[c][e][q];   // coalesced across lanes
            int   j = g_ni[c][e][q];
            if (j < 0 || j == q) d = CUDART_INF_F;   // invalid/self never inserts
            if (__ballot_sync(0xffffffffu, d < bd[NL - 1]))
                insert_branchless(d, j, bd, bi);
        }
    }

    float oq = op[q];
    float s = 0.0f;
#pragma unroll
    for (int k = 0; k < KNN; k++)
        s += fabsf(oq - op[bi[k]]);

    s = warp_sum(s);
    if ((threadIdx.x & 31) == 0) atomicAdd(&g_acc[3], s);
}

__global__ void final_kernel(float* __restrict__ out) {
    float sparsity  = g_acc[0] * (1.0f / NPTS);
    float opacity   = g_acc[1] * (1.0f / NPTS);
    float scale     = g_acc[2] * (1.0f / (3.0f * NPTS));
    float smooth    = g_acc[3] * (1.0f / ((float)NPTS * KNN));
    out[0] = 0.01f * sparsity + 0.1f * smooth + scale + opacity;
}

extern "C" void kernel_launch(void* const* d_in, const int* in_sizes, int n_in,
                              void* d_out, int out_size) {
    const float* pos = (const float*)d_in[0];
    const float* op  = (const float*)d_in[1];
    const float* sc  = (const float*)d_in[2];
    float* out = (float*)d_out;

    init_kernel<<<1, 32>>>();
    prep_kernel<<<NPTS / 256, 256>>>(pos, op, sc);
    boot_kernel<<<NPTS / QPB, QPB>>>(pos);
    knnb_kernel<<<(NPTS / QPB) * NCHB, QPB>>>(pos);
    merge_kernel<<<NPTS / 256, 256>>>(op);
    final_kernel<<<1, 1>>>(out);
}

// round 12
// speedup vs baseline: 1.7961x; 1.0150x over previous
#include <cuda_runtime.h>
#include <math_constants.h>

#define NPTS  16384
#define KNN   10
#define NL    11                 // K+1 slots per list (self may occupy one)
#define CH    1024               // candidates per chunk
#define NCH   16                 // chunk 0 = bootstrap, 1..15 = phase B
#define NCHB  (NCH - 1)
#define QPB   128                // threads per block
#define CAPB  32                 // knnb per-query quad-buffer capacity
#define CAP1  64                 // boot refine quad-buffer capacity
#define S0    64                 // boot forced-insert prefix

typedef unsigned long long ull;

// SoA components, quad-packed: (-2x, -2y, -2z, x^2+y^2+z^2)
__device__ float4 g_sx4[NPTS / 4], g_sy4[NPTS / 4], g_sz4[NPTS / 4], g_sw4[NPTS / 4];
// accumulators: 0 sparsity Σ|op|, 1 opacity Σ(op-.5)^2, 2 scale Σ|s-1|, 3 smooth Σ|Δop|
__device__ float g_acc[4];
// per-chunk candidate lists, t-space; [chunk][slot][q] for coalesced access
__device__ float g_nd[NCH][NL][NPTS];
__device__ int   g_ni[NCH][NL][NPTS];

// ---- f32x2 packed helpers (sm_103a) ----
__device__ __forceinline__ ull pack2(float lo, float hi) {
    ull r; asm("mov.b64 %0, {%1,%2};" : "=l"(r) : "f"(lo), "f"(hi)); return r;
}
__device__ __forceinline__ void unpack2(ull v, float& lo, float& hi) {
    asm("mov.b64 {%0,%1}, %2;" : "=f"(lo), "=f"(hi) : "l"(v));
}
__device__ __forceinline__ ull fma2(ull a, ull b, ull c) {
    ull d; asm("fma.rn.f32x2 %0, %1, %2, %3;" : "=l"(d) : "l"(a), "l"(b), "l"(c));
    return d;
}

__device__ __forceinline__ int mini(int a, int b) { return a < b ? a : b; }

__device__ __forceinline__ float warp_sum(float v) {
#pragma unroll
    for (int o = 16; o; o >>= 1) v += __shfl_xor_sync(0xffffffffu, v, o);
    return v;
}

__global__ void init_kernel() {
    if (threadIdx.x < 4) g_acc[threadIdx.x] = 0.0f;
}

__global__ void prep_kernel(const float* __restrict__ pos,
                            const float* __restrict__ op,
                            const float* __restrict__ sc) {
    int i = blockIdx.x * blockDim.x + threadIdx.x;   // grid covers exactly NPTS
    float x = pos[3 * i + 0], y = pos[3 * i + 1], z = pos[3 * i + 2];
    ((float*)g_sx4)[i] = -2.0f * x;
    ((float*)g_sy4)[i] = -2.0f * y;
    ((float*)g_sz4)[i] = -2.0f * z;
    ((float*)g_sw4)[i] = fmaf(z, z, fmaf(y, y, x * x));

    float o  = op[i];
    float sp = fabsf(o);
    float ol = (o - 0.5f) * (o - 0.5f);
    float sl = fabsf(sc[3 * i + 0] - 1.0f)
             + fabsf(sc[3 * i + 1] - 1.0f)
             + fabsf(sc[3 * i + 2] - 1.0f);
    sp = warp_sum(sp);
    ol = warp_sum(ol);
    sl = warp_sum(sl);
    if ((threadIdx.x & 31) == 0) {
        atomicAdd(&g_acc[0], sp);
        atomicAdd(&g_acc[1], ol);
        atomicAdd(&g_acc[2], sl);
    }
}

// branchless sorted insert: compares + select cascade (no inner branches)
__device__ __forceinline__ void insert_branchless(float d, int id,
                                                  float bd[NL], int bi[NL]) {
    bool lt[NL];
#pragma unroll
    for (int k = 0; k < NL; k++) lt[k] = d < bd[k];
#pragma unroll
    for (int k = NL - 1; k > 0; --k) {
        bd[k] = lt[k - 1] ? bd[k - 1] : (lt[k] ? d : bd[k]);
        bi[k] = lt[k - 1] ? bi[k - 1] : (lt[k] ? id : bi[k]);
    }
    bd[0] = lt[0] ? d : bd[0];
    bi[0] = lt[0] ? id : bi[0];
}

__device__ __forceinline__ float tscal(const float* fx, const float* fy,
                                       const float* fz, const float* fw, int c,
                                       float qx, float qy, float qz) {
    return fmaf(fx[c], qx, fmaf(fy[c], qy, fmaf(fz[c], qz, fw[c])));
}

// Bootstrap: exact top-11 of chunk 0 per query (t-space).
// Forced insert of first S0, then two buffered refine rounds.
// All buffered writes are CLAMPED to the trash slot; overflow -> exact rescan.
__global__ void __launch_bounds__(QPB) boot_kernel(const float* __restrict__ pos) {
    __shared__ float4 sx[CH / 4], sy[CH / 4], sz[CH / 4], sw[CH / 4];  // 16KB
    __shared__ unsigned char buf[QPB][CAP1 + 1];                       // 8.3KB

    const int q = blockIdx.x * QPB + threadIdx.x;
    const float qx = pos[3 * q + 0], qy = pos[3 * q + 1], qz = pos[3 * q + 2];

#pragma unroll
    for (int r = 0; r < CH / 4 / QPB; r++) {
        sx[r * QPB + threadIdx.x] = g_sx4[r * QPB + threadIdx.x];
        sy[r * QPB + threadIdx.x] = g_sy4[r * QPB + threadIdx.x];
        sz[r * QPB + threadIdx.x] = g_sz4[r * QPB + threadIdx.x];
        sw[r * QPB + threadIdx.x] = g_sw4[r * QPB + threadIdx.x];
    }
    __syncthreads();

    const float* fx = (const float*)sx;
    const float* fy = (const float*)sy;
    const float* fz = (const float*)sz;
    const float* fw = (const float*)sw;

    float bd[NL]; int bi[NL];
#pragma unroll
    for (int k = 0; k < NL; k++) { bd[k] = CUDART_INF_F; bi[k] = -1; }

    // stage 0: unconditional insert of first S0 candidates
#pragma unroll 1
    for (int c = 0; c < S0; c++)
        insert_branchless(tscal(fx, fy, fz, fw, c, qx, qy, qz), c, bd, bi);

    unsigned char* sbuf = buf[threadIdx.x];
    const ull qx2 = pack2(qx, qx), qy2 = pack2(qy, qy), qz2 = pack2(qz, qz);

    // round 1: c in [S0, 256) gated by 11th-of-64 (<=48 quads, fits CAP1)
    {
        const float thr = bd[NL - 1];
        int cnt = 0;
#pragma unroll 2
        for (int g = S0 / 4; g < 256 / 4; g++) {
            float4 X = sx[g], Y = sy[g], Z = sz[g], W = sw[g];
            ull t01 = fma2(pack2(X.x, X.y), qx2,
                      fma2(pack2(Y.x, Y.y), qy2,
                      fma2(pack2(Z.x, Z.y), qz2, pack2(W.x, W.y))));
            ull t23 = fma2(pack2(X.z, X.w), qx2,
                      fma2(pack2(Y.z, Y.w), qy2,
                      fma2(pack2(Z.z, Z.w), qz2, pack2(W.z, W.w))));
            float t0, t1, t2, t3;
            unpack2(t01, t0, t1); unpack2(t23, t2, t3);
            float m = fminf(fminf(t0, t1), fminf(t2, t3));
            bool pass = m < thr;
            sbuf[pass ? mini(cnt, CAP1) : CAP1] = (unsigned char)g;
            cnt += (int)pass;
        }
#pragma unroll 1
        for (int e = 0; e < cnt; e++) {
            int c4 = ((int)sbuf[e]) * 4;
#pragma unroll
            for (int u = 0; u < 4; u++) {
                float t = tscal(fx, fy, fz, fw, c4 + u, qx, qy, qz);
                if (t < bd[NL - 1]) insert_branchless(t, c4 + u, bd, bi);
            }
        }
    }

    // round 2: c in [256, 1024) gated by exact 11th-of-256 (clamped; fallback on overflow)
    {
        const float thr = bd[NL - 1];
        int cnt = 0;
#pragma unroll 2
        for (int g = 256 / 4; g < CH / 4; g++) {
            float4 X = sx[g], Y = sy[g], Z = sz[g], W = sw[g];
            ull t01 = fma2(pack2(X.x, X.y), qx2,
                      fma2(pack2(Y.x, Y.y), qy2,
                      fma2(pack2(Z.x, Z.y), qz2, pack2(W.x, W.y))));
            ull t23 = fma2(pack2(X.z, X.w), qx2,
                      fma2(pack2(Y.z, Y.w), qy2,
                      fma2(pack2(Z.z, Z.w), qz2, pack2(W.z, W.w))));
            float t0, t1, t2, t3;
            unpack2(t01, t0, t1); unpack2(t23, t2, t3);
            float m = fminf(fminf(t0, t1), fminf(t2, t3));
            bool pass = m < thr;
            sbuf[pass ? mini(cnt, CAP1) : CAP1] = (unsigned char)g;
            cnt += (int)pass;
        }
        if (cnt > CAP1) {
            // overflow fallback: exact rescan of [256, CH)
#pragma unroll 1
            for (int c = 256; c < CH; c++) {
                float t = tscal(fx, fy, fz, fw, c, qx, qy, qz);
                if (t < bd[NL - 1]) insert_branchless(t, c, bd, bi);
            }
        } else {
#pragma unroll 1
            for (int e = 0; e < cnt; e++) {
                int c4 = ((int)sbuf[e]) * 4;
#pragma unroll
                for (int u = 0; u < 4; u++) {
                    float t = tscal(fx, fy, fz, fw, c4 + u, qx, qy, qz);
                    if (t < bd[NL - 1]) insert_branchless(t, c4 + u, bd, bi);
                }
            }
        }
    }

#pragma unroll
    for (int k = 0; k < NL; k++) {
        g_nd[0][k][q] = bd[k];
        g_ni[0][k][q] = bi[k];
    }
}

// Phase B: chunks 1..15, seeded by chunk-0's 11th (upper bound on global 11th
// -> exact). 2 queries/thread, f32x2 packed math, predicated u8 quad buffers
// (clamped writes; overflow -> exact rescan).
// grid = (NPTS/(2*QPB)) * NCHB = 960 blocks of 128.
__global__ void __launch_bounds__(QPB) knnb_kernel(const float* __restrict__ pos) {
    __shared__ float4 sx[CH / 4], sy[CH / 4], sz[CH / 4], sw[CH / 4];  // 16KB
    __shared__ unsigned char buf[QPB][2][CAPB + 1];                    // 8.4KB

    const int chunk = 1 + (int)(blockIdx.x % NCHB);
    const int qA    = (int)(blockIdx.x / NCHB) * (2 * QPB) + threadIdx.x;
    const int qB    = qA + QPB;

    const float qxA = pos[3 * qA + 0], qyA = pos[3 * qA + 1], qzA = pos[3 * qA + 2];
    const float qxB = pos[3 * qB + 0], qyB = pos[3 * qB + 1], qzB = pos[3 * qB + 2];

    const int base  = chunk * CH;
    const int gbase = base / 4;
#pragma unroll
    for (int r = 0; r < CH / 4 / QPB; r++) {
        sx[r * QPB + threadIdx.x] = g_sx4[gbase + r * QPB + threadIdx.x];
        sy[r * QPB + threadIdx.x] = g_sy4[gbase + r * QPB + threadIdx.x];
        sz[r * QPB + threadIdx.x] = g_sz4[gbase + r * QPB + threadIdx.x];
        sw[r * QPB + threadIdx.x] = g_sw4[gbase + r * QPB + threadIdx.x];
    }
    __syncthreads();

    const float thrA = g_nd[0][NL - 1][qA];   // coalesced seed reads
    const float thrB = g_nd[0][NL - 1][qB];

    const ull qxA2 = pack2(qxA, qxA), qyA2 = pack2(qyA, qyA), qzA2 = pack2(qzA, qzA);
    const ull qxB2 = pack2(qxB, qxB), qyB2 = pack2(qyB, qyB), qzB2 = pack2(qzB, qzB);

    unsigned char* bufA = buf[threadIdx.x][0];
    unsigned char* bufB = buf[threadIdx.x][1];
    int cntA = 0, cntB = 0;

#pragma unroll 2
    for (int g = 0; g < CH / 4; g++) {
        float4 X = sx[g], Y = sy[g], Z = sz[g], W = sw[g];
        ull x01 = pack2(X.x, X.y), x23 = pack2(X.z, X.w);
        ull y01 = pack2(Y.x, Y.y), y23 = pack2(Y.z, Y.w);
        ull z01 = pack2(Z.x, Z.y), z23 = pack2(Z.z, Z.w);
        ull w01 = pack2(W.x, W.y), w23 = pack2(W.z, W.w);

        ull tA01 = fma2(x01, qxA2, fma2(y01, qyA2, fma2(z01, qzA2, w01)));
        ull tA23 = fma2(x23, qxA2, fma2(y23, qyA2, fma2(z23, qzA2, w23)));
        ull tB01 = fma2(x01, qxB2, fma2(y01, qyB2, fma2(z01, qzB2, w01)));
        ull tB23 = fma2(x23, qxB2, fma2(y23, qyB2, fma2(z23, qzB2, w23)));

        float a0, a1, a2, a3, b0, b1, b2, b3;
        unpack2(tA01, a0, a1); unpack2(tA23, a2, a3);
        unpack2(tB01, b0, b1); unpack2(tB23, b2, b3);

        float mA = fminf(fminf(a0, a1), fminf(a2, a3));
        float mB = fminf(fminf(b0, b1), fminf(b2, b3));

        bool pA = mA < thrA;
        bufA[pA ? mini(cntA, CAPB) : CAPB] = (unsigned char)g;
        cntA += (int)pA;
        bool pB = mB < thrB;
        bufB[pB ? mini(cntB, CAPB) : CAPB] = (unsigned char)g;
        cntB += (int)pB;
    }

    const float* fx = (const float*)sx;
    const float* fy = (const float*)sy;
    const float* fz = (const float*)sz;
    const float* fw = (const float*)sw;

    // ---- query A post-pass ----
    {
        float bd[NL]; int bi[NL];
#pragma unroll
        for (int k = 0; k < NL; k++) { bd[k] = thrA; bi[k] = -1; }
        if (cntA > CAPB) {
#pragma unroll 1
            for (int c = 0; c < CH; c++) {
                float t = tscal(fx, fy, fz, fw, c, qxA, qyA, qzA);
                if (t < bd[NL - 1]) insert_branchless(t, base + c, bd, bi);
            }
        } else {
#pragma unroll 1
            for (int e = 0; e < cntA; e++) {
                int c4 = ((int)bufA[e]) * 4;
#pragma unroll
                for (int u = 0; u < 4; u++) {
                    float t = tscal(fx, fy, fz, fw, c4 + u, qxA, qyA, qzA);
                    if (t < bd[NL - 1]) insert_branchless(t, base + c4 + u, bd, bi);
                }
            }
        }
#pragma unroll
        for (int k = 0; k < NL; k++) {
            g_nd[chunk][k][qA] = bd[k];
            g_ni[chunk][k][qA] = bi[k];
        }
    }

    // ---- query B post-pass ----
    {
        float bd[NL]; int bi[NL];
#pragma unroll
        for (int k = 0; k < NL; k++) { bd[k] = thrB; bi[k] = -1; }
        if (cntB > CAPB) {
#pragma unroll 1
            for (int c = 0; c < CH; c++) {
                float t = tscal(fx, fy, fz, fw, c, qxB, qyB, qzB);
                if (t < bd[NL - 1]) insert_branchless(t, base + c, bd, bi);
            }
        } else {
#pragma unroll 1
            for (int e = 0; e < cntB; e++) {
                int c4 = ((int)bufB[e]) * 4;
#pragma unroll
                for (int u = 0; u < 4; u++) {
                    float t = tscal(fx, fy, fz, fw, c4 + u, qxB, qyB, qzB);
                    if (t < bd[NL - 1]) insert_branchless(t, base + c4 + u, bd, bi);
                }
            }
        }
#pragma unroll
        for (int k = 0; k < NL; k++) {
            g_nd[chunk][k][qB] = bd[k];
            g_ni[chunk][k][qB] = bi[k];
        }
    }
}

// merge all NCH lists per query (filtering self/invalid), accumulate smoothness
__global__ void merge_kernel(const float* __restrict__ op) {
    int q = blockIdx.x * blockDim.x + threadIdx.x;

    float bd[NL]; int bi[NL];
#pragma unroll
    for (int k = 0; k < NL; k++) { bd[k] = CUDART_INF_F; bi[k] = -1; }

#pragma unroll 1
    for (int c = 0; c < NCH; c++) {
#pragma unroll 1
        for (int e = 0; e < NL; e++) {
            float d = g_nd[c][e][q];   // coalesced across lanes
            int   j = g_ni[c][e][q];
            if (j < 0 || j == q) d = CUDART_INF_F;   // invalid/self never inserts
            if (__ballot_sync(0xffffffffu, d < bd[NL - 1]))
                insert_branchless(d, j, bd, bi);
        }
    }

    float oq = op[q];
    float s = 0.0f;
#pragma unroll
    for (int k = 0; k < KNN; k++)
        s += fabsf(oq - op[bi[k]]);

    s = warp_sum(s);
    if ((threadIdx.x & 31) == 0) atomicAdd(&g_acc[3], s);
}

__global__ void final_kernel(float* __restrict__ out) {
    float sparsity  = g_acc[0] * (1.0f / NPTS);
    float opacity   = g_acc[1] * (1.0f / NPTS);
    float scale     = g_acc[2] * (1.0f / (3.0f * NPTS));
    float smooth    = g_acc[3] * (1.0f / ((float)NPTS * KNN));
    out[0] = 0.01f * sparsity + 0.1f * smooth + scale + opacity;
}

extern "C" void kernel_launch(void* const* d_in, const int* in_sizes, int n_in,
                              void* d_out, int out_size) {
    const float* pos = (const float*)d_in[0];
    const float* op  = (const float*)d_in[1];
    const float* sc  = (const float*)d_in[2];
    float* out = (float*)d_out;

    init_kernel<<<1, 32>>>();
    prep_kernel<<<NPTS / 256, 256>>>(pos, op, sc);
    boot_kernel<<<NPTS / QPB, QPB>>>(pos);
    knnb_kernel<<<(NPTS / (2 * QPB)) * NCHB, QPB>>>(pos);
    merge_kernel<<<NPTS / 128, 128>>>(op);
    final_kernel<<<1, 1>>>(out);
}

// round 13
// speedup vs baseline: 2.4364x; 1.3565x over previous
#include <cuda_runtime.h>
#include <math_constants.h>

#define NPTS   16384
#define KNN    10
#define NL     11                 // K+1 slots per list (self may occupy one)
#define BCH    1024               // bootstrap chunk (candidates 0..1023)
#define CHB    512                // phase-B chunk size
#define NCHB   30                 // phase-B chunk count: (NPTS - BCH) / CHB
#define NLISTS (1 + NCHB)         // list 0 = boot, 1..30 = phase B
#define QPB    128                // threads per block
#define CAPB   24                 // knnb per-query quad-buffer capacity
#define CAP1   64                 // boot refine quad-buffer capacity
#define S0     64                 // boot forced-insert prefix

typedef unsigned long long ull;

// SoA, quad-packed as ulonglong2 so LDS.128 directly yields f32x2 register
// pairs (no pack MOVs). Component semantics: (-2x, -2y, -2z, x^2+y^2+z^2).
__device__ ulonglong2 g_sx[NPTS / 4], g_sy[NPTS / 4], g_sz[NPTS / 4], g_sw[NPTS / 4];
// accumulators: 0 sparsity Σ|op|, 1 opacity Σ(op-.5)^2, 2 scale Σ|s-1|, 3 smooth Σ|Δop|
__device__ float g_acc[4];
// per-list candidate lists, t-space; [list][slot][q] for coalesced access
__device__ float g_nd[NLISTS][NL][NPTS];
__device__ int   g_ni[NLISTS][NL][NPTS];

// ---- f32x2 packed helpers (sm_103a) ----
__device__ __forceinline__ ull pack2(float lo, float hi) {
    ull r; asm("mov.b64 %0, {%1,%2};" : "=l"(r) : "f"(lo), "f"(hi)); return r;
}
__device__ __forceinline__ float2 asf2(ull v) {
    float2 r; asm("mov.b64 {%0,%1}, %2;" : "=f"(r.x), "=f"(r.y) : "l"(v));
    return r;
}
__device__ __forceinline__ ull fma2(ull a, ull b, ull c) {
    ull d; asm("fma.rn.f32x2 %0, %1, %2, %3;" : "=l"(d) : "l"(a), "l"(b), "l"(c));
    return d;
}

__device__ __forceinline__ int mini(int a, int b) { return a < b ? a : b; }

__device__ __forceinline__ float warp_sum(float v) {
#pragma unroll
    for (int o = 16; o; o >>= 1) v += __shfl_xor_sync(0xffffffffu, v, o);
    return v;
}

__global__ void init_kernel() {
    if (threadIdx.x < 4) g_acc[threadIdx.x] = 0.0f;
}

__global__ void prep_kernel(const float* __restrict__ pos,
                            const float* __restrict__ op,
                            const float* __restrict__ sc) {
    int i = blockIdx.x * blockDim.x + threadIdx.x;   // grid covers exactly NPTS
    float x = pos[3 * i + 0], y = pos[3 * i + 1], z = pos[3 * i + 2];
    ((float*)g_sx)[i] = -2.0f * x;
    ((float*)g_sy)[i] = -2.0f * y;
    ((float*)g_sz)[i] = -2.0f * z;
    ((float*)g_sw)[i] = fmaf(z, z, fmaf(y, y, x * x));

    float o  = op[i];
    float sp = fabsf(o);
    float ol = (o - 0.5f) * (o - 0.5f);
    float sl = fabsf(sc[3 * i + 0] - 1.0f)
             + fabsf(sc[3 * i + 1] - 1.0f)
             + fabsf(sc[3 * i + 2] - 1.0f);
    sp = warp_sum(sp);
    ol = warp_sum(ol);
    sl = warp_sum(sl);
    if ((threadIdx.x & 31) == 0) {
        atomicAdd(&g_acc[0], sp);
        atomicAdd(&g_acc[1], ol);
        atomicAdd(&g_acc[2], sl);
    }
}

// branchless sorted insert: compares + select cascade (no inner branches)
__device__ __forceinline__ void insert_branchless(float d, int id,
                                                  float bd[NL], int bi[NL]) {
    bool lt[NL];
#pragma unroll
    for (int k = 0; k < NL; k++) lt[k] = d < bd[k];
#pragma unroll
    for (int k = NL - 1; k > 0; --k) {
        bd[k] = lt[k - 1] ? bd[k - 1] : (lt[k] ? d : bd[k]);
        bi[k] = lt[k - 1] ? bi[k - 1] : (lt[k] ? id : bi[k]);
    }
    bd[0] = lt[0] ? d : bd[0];
    bi[0] = lt[0] ? id : bi[0];
}

__device__ __forceinline__ float tscal(const float* fx, const float* fy,
                                       const float* fz, const float* fw, int c,
                                       float qx, float qy, float qz) {
    return fmaf(fx[c], qx, fmaf(fy[c], qy, fmaf(fz[c], qz, fw[c])));
}

// quad t-values (packed): returns min of the 4, plus pass-through of pairs
__device__ __forceinline__ float quad_min(ulonglong2 X, ulonglong2 Y,
                                          ulonglong2 Z, ulonglong2 W,
                                          ull qx2, ull qy2, ull qz2) {
    ull t01 = fma2(X.x, qx2, fma2(Y.x, qy2, fma2(Z.x, qz2, W.x)));
    ull t23 = fma2(X.y, qx2, fma2(Y.y, qy2, fma2(Z.y, qz2, W.y)));
    float2 a = asf2(t01), b = asf2(t23);
    return fminf(fminf(a.x, a.y), fminf(b.x, b.y));
}

// Bootstrap: exact top-11 of candidates [0, BCH) per query (t-space).
// Forced insert of first S0, then two clamped buffered refine rounds.
__global__ void __launch_bounds__(QPB) boot_kernel(const float* __restrict__ pos) {
    __shared__ ulonglong2 sx[BCH / 4], sy[BCH / 4], sz[BCH / 4], sw[BCH / 4]; // 16KB
    __shared__ unsigned char buf[QPB][CAP1 + 1];                              // 8.3KB

    const int q = blockIdx.x * QPB + threadIdx.x;
    const float qx = pos[3 * q + 0], qy = pos[3 * q + 1], qz = pos[3 * q + 2];

#pragma unroll
    for (int r = 0; r < BCH / 4 / QPB; r++) {
        sx[r * QPB + threadIdx.x] = g_sx[r * QPB + threadIdx.x];
        sy[r * QPB + threadIdx.x] = g_sy[r * QPB + threadIdx.x];
        sz[r * QPB + threadIdx.x] = g_sz[r * QPB + threadIdx.x];
        sw[r * QPB + threadIdx.x] = g_sw[r * QPB + threadIdx.x];
    }
    __syncthreads();

    const float* fx = (const float*)sx;
    const float* fy = (const float*)sy;
    const float* fz = (const float*)sz;
    const float* fw = (const float*)sw;

    float bd[NL]; int bi[NL];
#pragma unroll
    for (int k = 0; k < NL; k++) { bd[k] = CUDART_INF_F; bi[k] = -1; }

    // stage 0: unconditional insert of first S0 candidates
#pragma unroll 1
    for (int c = 0; c < S0; c++)
        insert_branchless(tscal(fx, fy, fz, fw, c, qx, qy, qz), c, bd, bi);

    unsigned char* sbuf = buf[threadIdx.x];
    const ull qx2 = pack2(qx, qx), qy2 = pack2(qy, qy), qz2 = pack2(qz, qz);

    // round 1: c in [S0, 256) gated by 11th-of-64 (<=48 quads, fits CAP1)
    {
        const float thr = bd[NL - 1];
        int cnt = 0;
#pragma unroll 2
        for (int g = S0 / 4; g < 256 / 4; g++) {
            float m = quad_min(sx[g], sy[g], sz[g], sw[g], qx2, qy2, qz2);
            bool pass = m < thr;
            sbuf[pass ? mini(cnt, CAP1) : CAP1] = (unsigned char)g;
            cnt += (int)pass;
        }
#pragma unroll 1
        for (int e = 0; e < cnt; e++) {
            int c4 = ((int)sbuf[e]) * 4;
#pragma unroll
            for (int u = 0; u < 4; u++) {
                float t = tscal(fx, fy, fz, fw, c4 + u, qx, qy, qz);
                if (t < bd[NL - 1]) insert_branchless(t, c4 + u, bd, bi);
            }
        }
    }

    // round 2: c in [256, BCH) gated by exact 11th-of-256 (clamped; fallback)
    {
        const float thr = bd[NL - 1];
        int cnt = 0;
#pragma unroll 2
        for (int g = 256 / 4; g < BCH / 4; g++) {
            float m = quad_min(sx[g], sy[g], sz[g], sw[g], qx2, qy2, qz2);
            bool pass = m < thr;
            sbuf[pass ? mini(cnt, CAP1) : CAP1] = (unsigned char)g;
            cnt += (int)pass;
        }
        if (cnt > CAP1) {
            // overflow fallback: exact rescan of [256, BCH)
#pragma unroll 1
            for (int c = 256; c < BCH; c++) {
                float t = tscal(fx, fy, fz, fw, c, qx, qy, qz);
                if (t < bd[NL - 1]) insert_branchless(t, c, bd, bi);
            }
        } else {
#pragma unroll 1
            for (int e = 0; e < cnt; e++) {
                int c4 = ((int)sbuf[e]) * 4;
#pragma unroll
                for (int u = 0; u < 4; u++) {
                    float t = tscal(fx, fy, fz, fw, c4 + u, qx, qy, qz);
                    if (t < bd[NL - 1]) insert_branchless(t, c4 + u, bd, bi);
                }
            }
        }
    }

#pragma unroll
    for (int k = 0; k < NL; k++) {
        g_nd[0][k][q] = bd[k];
        g_ni[0][k][q] = bi[k];
    }
}

// Phase B: 30 chunks of 512 over candidates [BCH, NPTS), seeded by boot's
// 11th-of-1024 (upper bound on global 11th -> exact). 2 queries/thread,
// packed-pair tile (zero pack MOVs), clamped u8 quad buffers.
// grid = (NPTS/(2*QPB)) * NCHB = 1920 blocks of 128.
__global__ void __launch_bounds__(QPB) knnb_kernel(const float* __restrict__ pos) {
    __shared__ ulonglong2 sx[CHB / 4], sy[CHB / 4], sz[CHB / 4], sw[CHB / 4]; // 8KB
    __shared__ unsigned char buf[QPB][2][CAPB + 1];                           // 6.4KB

    const int l  = 1 + (int)(blockIdx.x % NCHB);
    const int qA = (int)(blockIdx.x / NCHB) * (2 * QPB) + threadIdx.x;
    const int qB = qA + QPB;

    const float qxA = pos[3 * qA + 0], qyA = pos[3 * qA + 1], qzA = pos[3 * qA + 2];
    const float qxB = pos[3 * qB + 0], qyB = pos[3 * qB + 1], qzB = pos[3 * qB + 2];

    const int base   = BCH + (l - 1) * CHB;
    const int gbase4 = base / 4;
    // CHB/4 = 128 quads: one per thread
    sx[threadIdx.x] = g_sx[gbase4 + threadIdx.x];
    sy[threadIdx.x] = g_sy[gbase4 + threadIdx.x];
    sz[threadIdx.x] = g_sz[gbase4 + threadIdx.x];
    sw[threadIdx.x] = g_sw[gbase4 + threadIdx.x];
    __syncthreads();

    const float thrA = g_nd[0][NL - 1][qA];   // coalesced seed reads
    const float thrB = g_nd[0][NL - 1][qB];

    const ull qxA2 = pack2(qxA, qxA), qyA2 = pack2(qyA, qyA), qzA2 = pack2(qzA, qzA);
    const ull qxB2 = pack2(qxB, qxB), qyB2 = pack2(qyB, qyB), qzB2 = pack2(qzB, qzB);

    unsigned char* bufA = buf[threadIdx.x][0];
    unsigned char* bufB = buf[threadIdx.x][1];
    int cntA = 0, cntB = 0;

#pragma unroll 4
    for (int g = 0; g < CHB / 4; g++) {
        ulonglong2 X = sx[g], Y = sy[g], Z = sz[g], W = sw[g];

        ull tA01 = fma2(X.x, qxA2, fma2(Y.x, qyA2, fma2(Z.x, qzA2, W.x)));
        ull tA23 = fma2(X.y, qxA2, fma2(Y.y, qyA2, fma2(Z.y, qzA2, W.y)));
        ull tB01 = fma2(X.x, qxB2, fma2(Y.x, qyB2, fma2(Z.x, qzB2, W.x)));
        ull tB23 = fma2(X.y, qxB2, fma2(Y.y, qyB2, fma2(Z.y, qzB2, W.y)));

        float2 a0 = asf2(tA01), a1 = asf2(tA23);
        float2 b0 = asf2(tB01), b1 = asf2(tB23);

        float mA = fminf(fminf(a0.x, a0.y), fminf(a1.x, a1.y));
        float mB = fminf(fminf(b0.x, b0.y), fminf(b1.x, b1.y));

        bool pA = mA < thrA;
        bufA[pA ? mini(cntA, CAPB) : CAPB] = (unsigned char)g;
        cntA += (int)pA;
        bool pB = mB < thrB;
        bufB[pB ? mini(cntB, CAPB) : CAPB] = (unsigned char)g;
        cntB += (int)pB;
    }

    const float* fx = (const float*)sx;
    const float* fy = (const float*)sy;
    const float* fz = (const float*)sz;
    const float* fw = (const float*)sw;

    // ---- query A post-pass ----
    {
        float bd[NL]; int bi[NL];
#pragma unroll
        for (int k = 0; k < NL; k++) { bd[k] = thrA; bi[k] = -1; }
        if (cntA > CAPB) {
#pragma unroll 1
            for (int c = 0; c < CHB; c++) {
                float t = tscal(fx, fy, fz, fw, c, qxA, qyA, qzA);
                if (t < bd[NL - 1]) insert_branchless(t, base + c, bd, bi);
            }
        } else {
#pragma unroll 1
            for (int e = 0; e < cntA; e++) {
                int c4 = ((int)bufA[e]) * 4;
#pragma unroll
                for (int u = 0; u < 4; u++) {
                    float t = tscal(fx, fy, fz, fw, c4 + u, qxA, qyA, qzA);
                    if (t < bd[NL - 1]) insert_branchless(t, base + c4 + u, bd, bi);
                }
            }
        }
#pragma unroll
        for (int k = 0; k < NL; k++) {
            g_nd[l][k][qA] = bd[k];
            g_ni[l][k][qA] = bi[k];
        }
    }

    // ---- query B post-pass ----
    {
        float bd[NL]; int bi[NL];
#pragma unroll
        for (int k = 0; k < NL; k++) { bd[k] = thrB; bi[k] = -1; }
        if (cntB > CAPB) {
#pragma unroll 1
            for (int c = 0; c < CHB; c++) {
                float t = tscal(fx, fy, fz, fw, c, qxB, qyB, qzB);
                if (t < bd[NL - 1]) insert_branchless(t, base + c, bd, bi);
            }
        } else {
#pragma unroll 1
            for (int e = 0; e < cntB; e++) {
                int c4 = ((int)bufB[e]) * 4;
#pragma unroll
                for (int u = 0; u < 4; u++) {
                    float t = tscal(fx, fy, fz, fw, c4 + u, qxB, qyB, qzB);
                    if (t < bd[NL - 1]) insert_branchless(t, base + c4 + u, bd, bi);
                }
            }
        }
#pragma unroll
        for (int k = 0; k < NL; k++) {
            g_nd[l][k][qB] = bd[k];
            g_ni[l][k][qB] = bi[k];
        }
    }
}

// merge all NLISTS lists per query (filtering self/invalid), accumulate smoothness
__global__ void merge_kernel(const float* __restrict__ op) {
    int q = blockIdx.x * blockDim.x + threadIdx.x;

    float bd[NL]; int bi[NL];
#pragma unroll
    for (int k = 0; k < NL; k++) { bd[k] = CUDART_INF_F; bi[k] = -1; }

#pragma unroll 1
    for (int c = 0; c < NLISTS; c++) {
        // hoisted loads: MLP=22 per list
        float dv[NL]; int jv[NL];
#pragma unroll
        for (int e = 0; e < NL; e++) {
            dv[e] = g_nd[c][e][q];   // coalesced across lanes
            jv[e] = g_ni[c][e][q];
        }
#pragma unroll
        for (int e = 0; e < NL; e++) {
            float d = dv[e];
            int   j = jv[e];
            if (j < 0 || j == q) d = CUDART_INF_F;   // invalid/self never inserts
            if (__ballot_sync(0xffffffffu, d < bd[NL - 1]))
                insert_branchless(d, j, bd, bi);
        }
    }

    float oq = op[q];
    float s = 0.0f;
#pragma unroll
    for (int k = 0; k < KNN; k++)
        s += fabsf(oq - op[bi[k]]);

    s = warp_sum(s);
    if ((threadIdx.x & 31) == 0) atomicAdd(&g_acc[3], s);
}

__global__ void final_kernel(float* __restrict__ out) {
    float sparsity  = g_acc[0] * (1.0f / NPTS);
    float opacity   = g_acc[1] * (1.0f / NPTS);
    float scale     = g_acc[2] * (1.0f / (3.0f * NPTS));
    float smooth    = g_acc[3] * (1.0f / ((float)NPTS * KNN));
    out[0] = 0.01f * sparsity + 0.1f * smooth + scale + opacity;
}

extern "C" void kernel_launch(void* const* d_in, const int* in_sizes, int n_in,
                              void* d_out, int out_size) {
    const float* pos = (const float*)d_in[0];
    const float* op  = (const float*)d_in[1];
    const float* sc  = (const float*)d_in[2];
    float* out = (float*)d_out;

    init_kernel<<<1, 32>>>();
    prep_kernel<<<NPTS / 256, 256>>>(pos, op, sc);
    boot_kernel<<<NPTS / QPB, QPB>>>(pos);
    knnb_kernel<<<(NPTS / (2 * QPB)) * NCHB, QPB>>>(pos);
    merge_kernel<<<NPTS / 128, 128>>>(op);
    final_kernel<<<1, 1>>>(out);
}

// round 14
// speedup vs baseline: 2.6851x; 1.1021x over previous
#include <cuda_runtime.h>
#include <math_constants.h>

#define NPTS   16384
#define KNN    10
#define NL     11                 // K+1 slots per list (self may occupy one)
#define BCH    512                // bootstrap half-chunk size (2 halves)
#define CHB    512                // phase-B chunk size
#define NCHB   30                 // phase-B chunks: (NPTS - 2*BCH) / CHB
#define NLISTS (2 + NCHB)         // lists 0,1 = boot halves, 2..31 = phase B
#define QPB    128                // threads per block
#define CAPB   40                 // knnb per-query quad-buffer capacity
#define CAP1   64                 // boot refine quad-buffer capacity
#define S0     64                 // boot forced-insert prefix

typedef unsigned long long ull;

// SoA, quad-packed as ulonglong2 so LDS.128 directly yields f32x2 register
// pairs (no pack MOVs). Component semantics: (-2x, -2y, -2z, x^2+y^2+z^2).
__device__ ulonglong2 g_sx[NPTS / 4], g_sy[NPTS / 4], g_sz[NPTS / 4], g_sw[NPTS / 4];
// accumulators: 0 sparsity Σ|op|, 1 opacity Σ(op-.5)^2, 2 scale Σ|s-1|, 3 smooth Σ|Δop|
__device__ float g_acc[4];
// per-list candidate lists, t-space; [list][slot][q] for coalesced access
__device__ float g_nd[NLISTS][NL][NPTS];
__device__ int   g_ni[NLISTS][NL][NPTS];

// ---- f32x2 packed helpers (sm_103a) ----
__device__ __forceinline__ ull pack2(float lo, float hi) {
    ull r; asm("mov.b64 %0, {%1,%2};" : "=l"(r) : "f"(lo), "f"(hi)); return r;
}
__device__ __forceinline__ float2 asf2(ull v) {
    float2 r; asm("mov.b64 {%0,%1}, %2;" : "=f"(r.x), "=f"(r.y) : "l"(v));
    return r;
}
__device__ __forceinline__ ull fma2(ull a, ull b, ull c) {
    ull d; asm("fma.rn.f32x2 %0, %1, %2, %3;" : "=l"(d) : "l"(a), "l"(b), "l"(c));
    return d;
}

__device__ __forceinline__ int mini(int a, int b) { return a < b ? a : b; }

__device__ __forceinline__ float warp_sum(float v) {
#pragma unroll
    for (int o = 16; o; o >>= 1) v += __shfl_xor_sync(0xffffffffu, v, o);
    return v;
}

__global__ void init_kernel() {
    if (threadIdx.x < 4) g_acc[threadIdx.x] = 0.0f;
}

__global__ void prep_kernel(const float* __restrict__ pos,
                            const float* __restrict__ op,
                            const float* __restrict__ sc) {
    int i = blockIdx.x * blockDim.x + threadIdx.x;   // grid covers exactly NPTS
    float x = pos[3 * i + 0], y = pos[3 * i + 1], z = pos[3 * i + 2];
    ((float*)g_sx)[i] = -2.0f * x;
    ((float*)g_sy)[i] = -2.0f * y;
    ((float*)g_sz)[i] = -2.0f * z;
    ((float*)g_sw)[i] = fmaf(z, z, fmaf(y, y, x * x));

    float o  = op[i];
    float sp = fabsf(o);
    float ol = (o - 0.5f) * (o - 0.5f);
    float sl = fabsf(sc[3 * i + 0] - 1.0f)
             + fabsf(sc[3 * i + 1] - 1.0f)
             + fabsf(sc[3 * i + 2] - 1.0f);
    sp = warp_sum(sp);
    ol = warp_sum(ol);
    sl = warp_sum(sl);
    if ((threadIdx.x & 31) == 0) {
        atomicAdd(&g_acc[0], sp);
        atomicAdd(&g_acc[1], ol);
        atomicAdd(&g_acc[2], sl);
    }
}

// branchless sorted insert: compares + select cascade (no inner branches)
__device__ __forceinline__ void insert_branchless(float d, int id,
                                                  float bd[NL], int bi[NL]) {
    bool lt[NL];
#pragma unroll
    for (int k = 0; k < NL; k++) lt[k] = d < bd[k];
#pragma unroll
    for (int k = NL - 1; k > 0; --k) {
        bd[k] = lt[k - 1] ? bd[k - 1] : (lt[k] ? d : bd[k]);
        bi[k] = lt[k - 1] ? bi[k - 1] : (lt[k] ? id : bi[k]);
    }
    bd[0] = lt[0] ? d : bd[0];
    bi[0] = lt[0] ? id : bi[0];
}

__device__ __forceinline__ float tscal(const float* fx, const float* fy,
                                       const float* fz, const float* fw, int c,
                                       float qx, float qy, float qz) {
    return fmaf(fx[c], qx, fmaf(fy[c], qy, fmaf(fz[c], qz, fw[c])));
}

// quad t-values (packed): min of the 4
__device__ __forceinline__ float quad_min(ulonglong2 X, ulonglong2 Y,
                                          ulonglong2 Z, ulonglong2 W,
                                          ull qx2, ull qy2, ull qz2) {
    ull t01 = fma2(X.x, qx2, fma2(Y.x, qy2, fma2(Z.x, qz2, W.x)));
    ull t23 = fma2(X.y, qx2, fma2(Y.y, qy2, fma2(Z.y, qz2, W.y)));
    float2 a = asf2(t01), b = asf2(t23);
    return fminf(fminf(a.x, a.y), fminf(b.x, b.y));
}

// Bootstrap: exact top-11 of one 512-candidate half per query (t-space).
// grid = (NPTS/QPB) * 2 = 256 blocks; block handles half = blockIdx & 1.
// Forced insert of first S0, then two clamped buffered refine rounds.
__global__ void __launch_bounds__(QPB) boot_kernel(const float* __restrict__ pos) {
    __shared__ ulonglong2 sx[BCH / 4], sy[BCH / 4], sz[BCH / 4], sw[BCH / 4]; // 8KB
    __shared__ unsigned char buf[QPB][CAP1 + 1];                              // 8.3KB

    const int half = blockIdx.x & 1;
    const int q    = (blockIdx.x >> 1) * QPB + threadIdx.x;
    const int base = half * BCH;
    const float qx = pos[3 * q + 0], qy = pos[3 * q + 1], qz = pos[3 * q + 2];

    // BCH/4 = 128 quads: one per thread
    sx[threadIdx.x] = g_sx[base / 4 + threadIdx.x];
    sy[threadIdx.x] = g_sy[base / 4 + threadIdx.x];
    sz[threadIdx.x] = g_sz[base / 4 + threadIdx.x];
    sw[threadIdx.x] = g_sw[base / 4 + threadIdx.x];
    __syncthreads();

    const float* fx = (const float*)sx;
    const float* fy = (const float*)sy;
    const float* fz = (const float*)sz;
    const float* fw = (const float*)sw;

    float bd[NL]; int bi[NL];
#pragma unroll
    for (int k = 0; k < NL; k++) { bd[k] = CUDART_INF_F; bi[k] = -1; }

    // stage 0: unconditional insert of first S0 candidates
#pragma unroll 1
    for (int c = 0; c < S0; c++)
        insert_branchless(tscal(fx, fy, fz, fw, c, qx, qy, qz), c, bd, bi);

    unsigned char* sbuf = buf[threadIdx.x];
    const ull qx2 = pack2(qx, qx), qy2 = pack2(qy, qy), qz2 = pack2(qz, qz);

    // round 1: c in [S0, 256) gated by 11th-of-64 (<=48 quads, fits CAP1)
    {
        const float thr = bd[NL - 1];
        int cnt = 0;
#pragma unroll 2
        for (int g = S0 / 4; g < 256 / 4; g++) {
            float m = quad_min(sx[g], sy[g], sz[g], sw[g], qx2, qy2, qz2);
            sbuf[mini(cnt, CAP1)] = (unsigned char)g;   // always-store; overwritten if !pass
            cnt += (int)(m < thr);
        }
#pragma unroll 1
        for (int e = 0; e < cnt; e++) {
            int c4 = ((int)sbuf[e]) * 4;
#pragma unroll
            for (int u = 0; u < 4; u++) {
                float t = tscal(fx, fy, fz, fw, c4 + u, qx, qy, qz);
                if (t < bd[NL - 1]) insert_branchless(t, c4 + u, bd, bi);
            }
        }
    }

    // round 2: c in [256, BCH) gated by exact 11th-of-256 (<=64 quads, fits CAP1)
    {
        const float thr = bd[NL - 1];
        int cnt = 0;
#pragma unroll 2
        for (int g = 256 / 4; g < BCH / 4; g++) {
            float m = quad_min(sx[g], sy[g], sz[g], sw[g], qx2, qy2, qz2);
            sbuf[mini(cnt, CAP1)] = (unsigned char)g;
            cnt += (int)(m < thr);
        }
#pragma unroll 1
        for (int e = 0; e < cnt; e++) {
            int c4 = ((int)sbuf[e]) * 4;
#pragma unroll
            for (int u = 0; u < 4; u++) {
                float t = tscal(fx, fy, fz, fw, c4 + u, qx, qy, qz);
                if (t < bd[NL - 1]) insert_branchless(t, c4 + u, bd, bi);
            }
        }
    }

#pragma unroll
    for (int k = 0; k < NL; k++) {
        g_nd[half][k][q] = bd[k];
        g_ni[half][k][q] = base + bi[k];   // bi is local; never -1 after 512 inserts
    }
}

// Phase B: 30 chunks of 512 over candidates [1024, NPTS), seeded by
// min(boot half thresholds) (upper bound on global 11th -> exact).
// 2 queries/thread, packed-pair tile, clamped always-store u8 quad buffers.
// grid = (NPTS/(2*QPB)) * NCHB = 1920 blocks of 128.
__global__ void __launch_bounds__(QPB) knnb_kernel(const float* __restrict__ pos) {
    __shared__ ulonglong2 sx[CHB / 4], sy[CHB / 4], sz[CHB / 4], sw[CHB / 4]; // 8KB
    __shared__ unsigned char buf[QPB][2][CAPB + 1];                           // 10.5KB

    const int l  = (int)(blockIdx.x % NCHB);
    const int qA = (int)(blockIdx.x / NCHB) * (2 * QPB) + threadIdx.x;
    const int qB = qA + QPB;

    const float qxA = pos[3 * qA + 0], qyA = pos[3 * qA + 1], qzA = pos[3 * qA + 2];
    const float qxB = pos[3 * qB + 0], qyB = pos[3 * qB + 1], qzB = pos[3 * qB + 2];

    const int base = 2 * BCH + l * CHB;
    // CHB/4 = 128 quads: one per thread
    sx[threadIdx.x] = g_sx[base / 4 + threadIdx.x];
    sy[threadIdx.x] = g_sy[base / 4 + threadIdx.x];
    sz[threadIdx.x] = g_sz[base / 4 + threadIdx.x];
    sw[threadIdx.x] = g_sw[base / 4 + threadIdx.x];
    __syncthreads();

    const float thrA = fminf(g_nd[0][NL - 1][qA], g_nd[1][NL - 1][qA]);
    const float thrB = fminf(g_nd[0][NL - 1][qB], g_nd[1][NL - 1][qB]);

    const ull qxA2 = pack2(qxA, qxA), qyA2 = pack2(qyA, qyA), qzA2 = pack2(qzA, qzA);
    const ull qxB2 = pack2(qxB, qxB), qyB2 = pack2(qyB, qyB), qzB2 = pack2(qzB, qzB);

    unsigned char* bufA = buf[threadIdx.x][0];
    unsigned char* bufB = buf[threadIdx.x][1];
    int cntA = 0, cntB = 0;

#pragma unroll 8
    for (int g = 0; g < CHB / 4; g++) {
        ulonglong2 X = sx[g], Y = sy[g], Z = sz[g], W = sw[g];

        ull tA01 = fma2(X.x, qxA2, fma2(Y.x, qyA2, fma2(Z.x, qzA2, W.x)));
        ull tA23 = fma2(X.y, qxA2, fma2(Y.y, qyA2, fma2(Z.y, qzA2, W.y)));
        ull tB01 = fma2(X.x, qxB2, fma2(Y.x, qyB2, fma2(Z.x, qzB2, W.x)));
        ull tB23 = fma2(X.y, qxB2, fma2(Y.y, qyB2, fma2(Z.y, qzB2, W.y)));

        float2 a0 = asf2(tA01), a1 = asf2(tA23);
        float2 b0 = asf2(tB01), b1 = asf2(tB23);

        float mA = fminf(fminf(a0.x, a0.y), fminf(a1.x, a1.y));
        float mB = fminf(fminf(b0.x, b0.y), fminf(b1.x, b1.y));

        // always-store at the open slot; only passing stores advance cnt
        bufA[mini(cntA, CAPB)] = (unsigned char)g;
        cntA += (int)(mA < thrA);
        bufB[mini(cntB, CAPB)] = (unsigned char)g;
        cntB += (int)(mB < thrB);
    }

    const float* fx = (const float*)sx;
    const float* fy = (const float*)sy;
    const float* fz = (const float*)sz;
    const float* fw = (const float*)sw;

    // ---- query A post-pass ----
    {
        float bd[NL]; int bi[NL];
#pragma unroll
        for (int k = 0; k < NL; k++) { bd[k] = thrA; bi[k] = -1; }
        if (cntA > CAPB) {
#pragma unroll 1
            for (int c = 0; c < CHB; c++) {
                float t = tscal(fx, fy, fz, fw, c, qxA, qyA, qzA);
                if (t < bd[NL - 1]) insert_branchless(t, base + c, bd, bi);
            }
        } else {
#pragma unroll 1
            for (int e = 0; e < cntA; e++) {
                int c4 = ((int)bufA[e]) * 4;
#pragma unroll
                for (int u = 0; u < 4; u++) {
                    float t = tscal(fx, fy, fz, fw, c4 + u, qxA, qyA, qzA);
                    if (t < bd[NL - 1]) insert_branchless(t, base + c4 + u, bd, bi);
                }
            }
        }
#pragma unroll
        for (int k = 0; k < NL; k++) {
            g_nd[2 + l][k][qA] = bd[k];
            g_ni[2 + l][k][qA] = bi[k];
        }
    }

    // ---- query B post-pass ----
    {
        float bd[NL]; int bi[NL];
#pragma unroll
        for (int k = 0; k < NL; k++) { bd[k] = thrB; bi[k] = -1; }
        if (cntB > CAPB) {
#pragma unroll 1
            for (int c = 0; c < CHB; c++) {
                float t = tscal(fx, fy, fz, fw, c, qxB, qyB, qzB);
                if (t < bd[NL - 1]) insert_branchless(t, base + c, bd, bi);
            }
        } else {
#pragma unroll 1
            for (int e = 0; e < cntB; e++) {
                int c4 = ((int)bufB[e]) * 4;
#pragma unroll
                for (int u = 0; u < 4; u++) {
                    float t = tscal(fx, fy, fz, fw, c4 + u, qxB, qyB, qzB);
                    if (t < bd[NL - 1]) insert_branchless(t, base + c4 + u, bd, bi);
                }
            }
        }
#pragma unroll
        for (int k = 0; k < NL; k++) {
            g_nd[2 + l][k][qB] = bd[k];
            g_ni[2 + l][k][qB] = bi[k];
        }
    }
}

// merge all NLISTS lists per query (filtering self/invalid), accumulate smoothness
__global__ void merge_kernel(const float* __restrict__ op) {
    int q = blockIdx.x * blockDim.x + threadIdx.x;

    float bd[NL]; int bi[NL];
#pragma unroll
    for (int k = 0; k < NL; k++) { bd[k] = CUDART_INF_F; bi[k] = -1; }

#pragma unroll 1
    for (int c = 0; c < NLISTS; c++) {
        // hoisted loads: MLP=22 per list
        float dv[NL]; int jv[NL];
#pragma unroll
        for (int e = 0; e < NL; e++) {
            dv[e] = g_nd[c][e][q];   // coalesced across lanes
            jv[e] = g_ni[c][e][q];
        }
#pragma unroll
        for (int e = 0; e < NL; e++) {
            float d = dv[e];
            int   j = jv[e];
            if (j < 0 || j == q) d = CUDART_INF_F;   // invalid/self never inserts
            if (__ballot_sync(0xffffffffu, d < bd[NL - 1]))
                insert_branchless(d, j, bd, bi);
        }
    }

    float oq = op[q];
    float s = 0.0f;
#pragma unroll
    for (int k = 0; k < KNN; k++)
        s += fabsf(oq - op[bi[k]]);

    s = warp_sum(s);
    if ((threadIdx.x & 31) == 0) atomicAdd(&g_acc[3], s);
}

__global__ void final_kernel(float* __restrict__ out) {
    float sparsity  = g_acc[0] * (1.0f / NPTS);
    float opacity   = g_acc[1] * (1.0f / NPTS);
    float scale     = g_acc[2] * (1.0f / (3.0f * NPTS));
    float smooth    = g_acc[3] * (1.0f / ((float)NPTS * KNN));
    out[0] = 0.01f * sparsity + 0.1f * smooth + scale + opacity;
}

extern "C" void kernel_launch(void* const* d_in, const int* in_sizes, int n_in,
                              void* d_out, int out_size) {
    const float* pos = (const float*)d_in[0];
    const float* op  = (const float*)d_in[1];
    const float* sc  = (const float*)d_in[2];
    float* out = (float*)d_out;

    init_kernel<<<1, 32>>>();
    prep_kernel<<<NPTS / 256, 256>>>(pos, op, sc);
    boot_kernel<<<(NPTS / QPB) * 2, QPB>>>(pos);
    knnb_kernel<<<(NPTS / (2 * QPB)) * NCHB, QPB>>>(pos);
    merge_kernel<<<NPTS / 128, 128>>>(op);
    final_kernel<<<1, 1>>>(out);
}

// round 15
// speedup vs baseline: 2.9991x; 1.1170x over previous
#include <cuda_runtime.h>
#include <math_constants.h>

#define NPTS   16384
#define KNN    10
#define NL     11                 // K+1 slots per list (self may occupy one)
#define BCH    512                // bootstrap half-chunk size (2 halves)
#define CHB    512                // phase-B chunk size
#define NCHB   30                 // phase-B chunks: (NPTS - 2*BCH) / CHB
#define NLISTS (2 + NCHB)         // lists 0,1 = boot halves, 2..31 = phase B
#define QPB    128                // threads per block
#define CAPB   24                 // knnb per-query quad-buffer capacity
#define CAP1   64                 // boot refine quad-buffer capacity
#define S0     64                 // boot forced-insert prefix

typedef unsigned long long ull;

// SoA, quad-packed as ulonglong2 so LDS.128 directly yields f32x2 register
// pairs (no pack MOVs). Component semantics: (-2x, -2y, -2z, x^2+y^2+z^2).
__device__ ulonglong2 g_sx[NPTS / 4], g_sy[NPTS / 4], g_sz[NPTS / 4], g_sw[NPTS / 4];
// accumulators: 0 sparsity Σ|op|, 1 opacity Σ(op-.5)^2, 2 scale Σ|s-1|, 3 smooth Σ|Δop|
__device__ float g_acc[4];
// exact 11th-of-1024 t-threshold per query (from merging boot halves)
__device__ float g_thr[NPTS];
// per-list candidate lists, t-space; [list][slot][q] for coalesced access
__device__ float g_nd[NLISTS][NL][NPTS];
__device__ int   g_ni[NLISTS][NL][NPTS];

// ---- f32x2 packed helpers (sm_103a) ----
__device__ __forceinline__ ull pack2(float lo, float hi) {
    ull r; asm("mov.b64 %0, {%1,%2};" : "=l"(r) : "f"(lo), "f"(hi)); return r;
}
__device__ __forceinline__ float2 asf2(ull v) {
    float2 r; asm("mov.b64 {%0,%1}, %2;" : "=f"(r.x), "=f"(r.y) : "l"(v));
    return r;
}
__device__ __forceinline__ ull fma2(ull a, ull b, ull c) {
    ull d; asm("fma.rn.f32x2 %0, %1, %2, %3;" : "=l"(d) : "l"(a), "l"(b), "l"(c));
    return d;
}

__device__ __forceinline__ int mini(int a, int b) { return a < b ? a : b; }

__device__ __forceinline__ float warp_sum(float v) {
#pragma unroll
    for (int o = 16; o; o >>= 1) v += __shfl_xor_sync(0xffffffffu, v, o);
    return v;
}

__global__ void init_kernel() {
    if (threadIdx.x < 4) g_acc[threadIdx.x] = 0.0f;
}

__global__ void prep_kernel(const float* __restrict__ pos,
                            const float* __restrict__ op,
                            const float* __restrict__ sc) {
    int i = blockIdx.x * blockDim.x + threadIdx.x;   // grid covers exactly NPTS
    float x = pos[3 * i + 0], y = pos[3 * i + 1], z = pos[3 * i + 2];
    ((float*)g_sx)[i] = -2.0f * x;
    ((float*)g_sy)[i] = -2.0f * y;
    ((float*)g_sz)[i] = -2.0f * z;
    ((float*)g_sw)[i] = fmaf(z, z, fmaf(y, y, x * x));

    float o  = op[i];
    float sp = fabsf(o);
    float ol = (o - 0.5f) * (o - 0.5f);
    float sl = fabsf(sc[3 * i + 0] - 1.0f)
             + fabsf(sc[3 * i + 1] - 1.0f)
             + fabsf(sc[3 * i + 2] - 1.0f);
    sp = warp_sum(sp);
    ol = warp_sum(ol);
    sl = warp_sum(sl);
    if ((threadIdx.x & 31) == 0) {
        atomicAdd(&g_acc[0], sp);
        atomicAdd(&g_acc[1], ol);
        atomicAdd(&g_acc[2], sl);
    }
}

// branchless sorted insert: compares + select cascade (no inner branches)
__device__ __forceinline__ void insert_branchless(float d, int id,
                                                  float bd[NL], int bi[NL]) {
    bool lt[NL];
#pragma unroll
    for (int k = 0; k < NL; k++) lt[k] = d < bd[k];
#pragma unroll
    for (int k = NL - 1; k > 0; --k) {
        bd[k] = lt[k - 1] ? bd[k - 1] : (lt[k] ? d : bd[k]);
        bi[k] = lt[k - 1] ? bi[k - 1] : (lt[k] ? id : bi[k]);
    }
    bd[0] = lt[0] ? d : bd[0];
    bi[0] = lt[0] ? id : bi[0];
}

// value-only branchless sorted insert (for threshold merging)
__device__ __forceinline__ void insert_val(float d, float bd[NL]) {
    bool lt[NL];
#pragma unroll
    for (int k = 0; k < NL; k++) lt[k] = d < bd[k];
#pragma unroll
    for (int k = NL - 1; k > 0; --k)
        bd[k] = lt[k - 1] ? bd[k - 1] : (lt[k] ? d : bd[k]);
    bd[0] = lt[0] ? d : bd[0];
}

__device__ __forceinline__ float tscal(const float* fx, const float* fy,
                                       const float* fz, const float* fw, int c,
                                       float qx, float qy, float qz) {
    return fmaf(fx[c], qx, fmaf(fy[c], qy, fmaf(fz[c], qz, fw[c])));
}

// quad t-values (packed): min of the 4
__device__ __forceinline__ float quad_min(ulonglong2 X, ulonglong2 Y,
                                          ulonglong2 Z, ulonglong2 W,
                                          ull qx2, ull qy2, ull qz2) {
    ull t01 = fma2(X.x, qx2, fma2(Y.x, qy2, fma2(Z.x, qz2, W.x)));
    ull t23 = fma2(X.y, qx2, fma2(Y.y, qy2, fma2(Z.y, qz2, W.y)));
    float2 a = asf2(t01), b = asf2(t23);
    return fminf(fminf(a.x, a.y), fminf(b.x, b.y));
}

// Bootstrap: exact top-11 of one 512-candidate half per query (t-space).
// grid = (NPTS/QPB) * 2 = 256 blocks; block handles half = blockIdx & 1.
__global__ void __launch_bounds__(QPB) boot_kernel(const float* __restrict__ pos) {
    __shared__ ulonglong2 sx[BCH / 4], sy[BCH / 4], sz[BCH / 4], sw[BCH / 4]; // 8KB
    __shared__ unsigned char buf[QPB][CAP1 + 1];                              // 8.3KB

    const int half = blockIdx.x & 1;
    const int q    = (blockIdx.x >> 1) * QPB + threadIdx.x;
    const int base = half * BCH;
    const float qx = pos[3 * q + 0], qy = pos[3 * q + 1], qz = pos[3 * q + 2];

    // BCH/4 = 128 quads: one per thread
    sx[threadIdx.x] = g_sx[base / 4 + threadIdx.x];
    sy[threadIdx.x] = g_sy[base / 4 + threadIdx.x];
    sz[threadIdx.x] = g_sz[base / 4 + threadIdx.x];
    sw[threadIdx.x] = g_sw[base / 4 + threadIdx.x];
    __syncthreads();

    const float* fx = (const float*)sx;
    const float* fy = (const float*)sy;
    const float* fz = (const float*)sz;
    const float* fw = (const float*)sw;

    float bd[NL]; int bi[NL];
#pragma unroll
    for (int k = 0; k < NL; k++) { bd[k] = CUDART_INF_F; bi[k] = -1; }

    // stage 0: unconditional insert of first S0 candidates
#pragma unroll 1
    for (int c = 0; c < S0; c++)
        insert_branchless(tscal(fx, fy, fz, fw, c, qx, qy, qz), c, bd, bi);

    unsigned char* sbuf = buf[threadIdx.x];
    const ull qx2 = pack2(qx, qx), qy2 = pack2(qy, qy), qz2 = pack2(qz, qz);

    // round 1: c in [S0, 256) gated by 11th-of-64 (<=48 quads, fits CAP1)
    {
        const float thr = bd[NL - 1];
        int cnt = 0;
#pragma unroll 2
        for (int g = S0 / 4; g < 256 / 4; g++) {
            float m = quad_min(sx[g], sy[g], sz[g], sw[g], qx2, qy2, qz2);
            sbuf[mini(cnt, CAP1)] = (unsigned char)g;   // always-store; overwritten if !pass
            cnt += (int)(m < thr);
        }
#pragma unroll 1
        for (int e = 0; e < cnt; e++) {
            int c4 = ((int)sbuf[e]) * 4;
#pragma unroll
            for (int u = 0; u < 4; u++) {
                float t = tscal(fx, fy, fz, fw, c4 + u, qx, qy, qz);
                if (t < bd[NL - 1]) insert_branchless(t, c4 + u, bd, bi);
            }
        }
    }

    // round 2: c in [256, BCH) gated by exact 11th-of-256 (<=64 quads, fits CAP1)
    {
        const float thr = bd[NL - 1];
        int cnt = 0;
#pragma unroll 2
        for (int g = 256 / 4; g < BCH / 4; g++) {
            float m = quad_min(sx[g], sy[g], sz[g], sw[g], qx2, qy2, qz2);
            sbuf[mini(cnt, CAP1)] = (unsigned char)g;
            cnt += (int)(m < thr);
        }
#pragma unroll 1
        for (int e = 0; e < cnt; e++) {
            int c4 = ((int)sbuf[e]) * 4;
#pragma unroll
            for (int u = 0; u < 4; u++) {
                float t = tscal(fx, fy, fz, fw, c4 + u, qx, qy, qz);
                if (t < bd[NL - 1]) insert_branchless(t, c4 + u, bd, bi);
            }
        }
    }

#pragma unroll
    for (int k = 0; k < NL; k++) {
        g_nd[half][k][q] = bd[k];
        g_ni[half][k][q] = base + bi[k];   // bi is local; never -1 after 512 inserts
    }
}

// Threshold merge: exact 11th-of-1024 per query from the two boot half lists.
// (top-11 of a union is contained in the union of the per-half top-11s)
__global__ void thr_kernel() {
    int q = blockIdx.x * blockDim.x + threadIdx.x;
    float bd[NL];
#pragma unroll
    for (int k = 0; k < NL; k++) bd[k] = g_nd[0][k][q];   // already sorted
#pragma unroll
    for (int k = 0; k < NL; k++) insert_val(g_nd[1][k][q], bd);
    g_thr[q] = bd[NL - 1];
}

// Phase B: 30 chunks of 512 over candidates [1024, NPTS), seeded by the exact
// 11th-of-1024 threshold (upper bound on global 11th -> exact).
// 2 queries/thread, packed-pair tile, clamped always-store u8 quad buffers.
// grid = (NPTS/(2*QPB)) * NCHB = 1920 blocks of 128.
__global__ void __launch_bounds__(QPB) knnb_kernel(const float* __restrict__ pos) {
    __shared__ ulonglong2 sx[CHB / 4], sy[CHB / 4], sz[CHB / 4], sw[CHB / 4]; // 8KB
    __shared__ unsigned char buf[QPB][2][CAPB + 1];                           // 6.4KB

    const int l  = (int)(blockIdx.x % NCHB);
    const int qA = (int)(blockIdx.x / NCHB) * (2 * QPB) + threadIdx.x;
    const int qB = qA + QPB;

    const float qxA = pos[3 * qA + 0], qyA = pos[3 * qA + 1], qzA = pos[3 * qA + 2];
    const float qxB = pos[3 * qB + 0], qyB = pos[3 * qB + 1], qzB = pos[3 * qB + 2];

    const int base = 2 * BCH + l * CHB;
    // CHB/4 = 128 quads: one per thread
    sx[threadIdx.x] = g_sx[base / 4 + threadIdx.x];
    sy[threadIdx.x] = g_sy[base / 4 + threadIdx.x];
    sz[threadIdx.x] = g_sz[base / 4 + threadIdx.x];
    sw[threadIdx.x] = g_sw[base / 4 + threadIdx.x];
    __syncthreads();

    const float thrA = g_thr[qA];   // exact 11-of-1024 (coalesced)
    const float thrB = g_thr[qB];

    const ull qxA2 = pack2(qxA, qxA), qyA2 = pack2(qyA, qyA), qzA2 = pack2(qzA, qzA);
    const ull qxB2 = pack2(qxB, qxB), qyB2 = pack2(qyB, qyB), qzB2 = pack2(qzB, qzB);

    unsigned char* bufA = buf[threadIdx.x][0];
    unsigned char* bufB = buf[threadIdx.x][1];
    int cntA = 0, cntB = 0;

#pragma unroll 4
    for (int g = 0; g < CHB / 4; g++) {
        ulonglong2 X = sx[g], Y = sy[g], Z = sz[g], W = sw[g];

        ull tA01 = fma2(X.x, qxA2, fma2(Y.x, qyA2, fma2(Z.x, qzA2, W.x)));
        ull tA23 = fma2(X.y, qxA2, fma2(Y.y, qyA2, fma2(Z.y, qzA2, W.y)));
        ull tB01 = fma2(X.x, qxB2, fma2(Y.x, qyB2, fma2(Z.x, qzB2, W.x)));
        ull tB23 = fma2(X.y, qxB2, fma2(Y.y, qyB2, fma2(Z.y, qzB2, W.y)));

        float2 a0 = asf2(tA01), a1 = asf2(tA23);
        float2 b0 = asf2(tB01), b1 = asf2(tB23);

        float mA = fminf(fminf(a0.x, a0.y), fminf(a1.x, a1.y));
        float mB = fminf(fminf(b0.x, b0.y), fminf(b1.x, b1.y));

        // always-store at the open slot; only passing stores advance cnt
        bufA[mini(cntA, CAPB)] = (unsigned char)g;
        cntA += (int)(mA < thrA);
        bufB[mini(cntB, CAPB)] = (unsigned char)g;
        cntB += (int)(mB < thrB);
    }

    const float* fx = (const float*)sx;
    const float* fy = (const float*)sy;
    const float* fz = (const float*)sz;
    const float* fw = (const float*)sw;

    // ---- query A post-pass ----
    {
        float bd[NL]; int bi[NL];
#pragma unroll
        for (int k = 0; k < NL; k++) { bd[k] = thrA; bi[k] = -1; }
        if (cntA > CAPB) {
#pragma unroll 1
            for (int c = 0; c < CHB; c++) {
                float t = tscal(fx, fy, fz, fw, c, qxA, qyA, qzA);
                if (t < bd[NL - 1]) insert_branchless(t, base + c, bd, bi);
            }
        } else {
#pragma unroll 1
            for (int e = 0; e < cntA; e++) {
                int c4 = ((int)bufA[e]) * 4;
#pragma unroll
                for (int u = 0; u < 4; u++) {
                    float t = tscal(fx, fy, fz, fw, c4 + u, qxA, qyA, qzA);
                    if (t < bd[NL - 1]) insert_branchless(t, base + c4 + u, bd, bi);
                }
            }
        }
#pragma unroll
        for (int k = 0; k < NL; k++) {
            g_nd[2 + l][k][qA] = bd[k];
            g_ni[2 + l][k][qA] = bi[k];
        }
    }

    // ---- query B post-pass ----
    {
        float bd[NL]; int bi[NL];
#pragma unroll
        for (int k = 0; k < NL; k++) { bd[k] = thrB; bi[k] = -1; }
        if (cntB > CAPB) {
#pragma unroll 1
            for (int c = 0; c < CHB; c++) {
                float t = tscal(fx, fy, fz, fw, c, qxB, qyB, qzB);
                if (t < bd[NL - 1]) insert_branchless(t, base + c, bd, bi);
            }
        } else {
#pragma unroll 1
            for (int e = 0; e < cntB; e++) {
                int c4 = ((int)bufB[e]) * 4;
#pragma unroll
                for (int u = 0; u < 4; u++) {
                    float t = tscal(fx, fy, fz, fw, c4 + u, qxB, qyB, qzB);
                    if (t < bd[NL - 1]) insert_branchless(t, base + c4 + u, bd, bi);
                }
            }
        }
#pragma unroll
        for (int k = 0; k < NL; k++) {
            g_nd[2 + l][k][qB] = bd[k];
            g_ni[2 + l][k][qB] = bi[k];
        }
    }
}

// merge all NLISTS lists per query (filtering self/invalid), accumulate smoothness
__global__ void merge_kernel(const float* __restrict__ op) {
    int q = blockIdx.x * blockDim.x + threadIdx.x;

    float bd[NL]; int bi[NL];
#pragma unroll
    for (int k = 0; k < NL; k++) { bd[k] = CUDART_INF_F; bi[k] = -1; }

#pragma unroll 1
    for (int c = 0; c < NLISTS; c++) {
        // hoisted loads: MLP=22 per list
        float dv[NL]; int jv[NL];
#pragma unroll
        for (int e = 0; e < NL; e++) {
            dv[e] = g_nd[c][e][q];   // coalesced across lanes
            jv[e] = g_ni[c][e][q];
        }
#pragma unroll
        for (int e = 0; e < NL; e++) {
            float d = dv[e];
            int   j = jv[e];
            if (j < 0 || j == q) d = CUDART_INF_F;   // invalid/self never inserts
            if (__ballot_sync(0xffffffffu, d < bd[NL - 1]))
                insert_branchless(d, j, bd, bi);
        }
    }

    float oq = op[q];
    float s = 0.0f;
#pragma unroll
    for (int k = 0; k < KNN; k++)
        s += fabsf(oq - op[bi[k]]);

    s = warp_sum(s);
    if ((threadIdx.x & 31) == 0) atomicAdd(&g_acc[3], s);
}

__global__ void final_kernel(float* __restrict__ out) {
    float sparsity  = g_acc[0] * (1.0f / NPTS);
    float opacity   = g_acc[1] * (1.0f / NPTS);
    float scale     = g_acc[2] * (1.0f / (3.0f * NPTS));
    float smooth    = g_acc[3] * (1.0f / ((float)NPTS * KNN));
    out[0] = 0.01f * sparsity + 0.1f * smooth + scale + opacity;
}

extern "C" void kernel_launch(void* const* d_in, const int* in_sizes, int n_in,
                              void* d_out, int out_size) {
    const float* pos = (const float*)d_in[0];
    const float* op  = (const float*)d_in[1];
    const float* sc  = (const float*)d_in[2];
    float* out = (float*)d_out;

    init_kernel<<<1, 32>>>();
    prep_kernel<<<NPTS / 256, 256>>>(pos, op, sc);
    boot_kernel<<<(NPTS / QPB) * 2, QPB>>>(pos);
    thr_kernel<<<NPTS / 256, 256>>>();
    knnb_kernel<<<(NPTS / (2 * QPB)) * NCHB, QPB>>>(pos);
    merge_kernel<<<NPTS / 128, 128>>>(op);
    final_kernel<<<1, 1>>>(out);
}

// round 17
// speedup vs baseline: 3.0799x; 1.0269x over previous
#include <cuda_runtime.h>
#include <math_constants.h>

#define NPTS   16384
#define KNN    10
#define NL     11                 // K+1 slots per list (self may occupy one)
#define BCH    512                // bootstrap half-chunk size (2 halves)
#define CHB    512                // phase-B chunk size
#define NCHB   30                 // phase-B chunks: (NPTS - 2*BCH) / CHB
#define NLISTS (2 + NCHB)         // lists 0,1 = boot halves, 2..31 = phase B
#define QPB    128                // threads per block
#define S0     32                 // boot forced-insert prefix
#define BUFW   100                // per-thread smem buffer bytes (25 words, coprime 32)
#define OFFB   34                 // B-query sub-buffer offset within region
#define BLIM   99                 // clamp limit for B pointer (stays in own pad)

typedef unsigned long long ull;

// SoA, quad-packed as ulonglong2 so LDS.128 directly yields f32x2 register
// pairs (no pack MOVs). Component semantics: (-2x, -2y, -2z, x^2+y^2+z^2).
__device__ ulonglong2 g_sx[NPTS / 4], g_sy[NPTS / 4], g_sz[NPTS / 4], g_sw[NPTS / 4];
// per-prep-block partial sums: x=sparsity, y=opacity, z=scale
__device__ float3 g_part[64];
// smoothness accumulator (zeroed by thr_kernel, added by merge_kernel)
__device__ float g_smooth;
// exact 11th-of-1024 t-threshold per query (from merging boot halves)
__device__ float g_thr[NPTS];
// per-list candidate lists, t-space; [list][slot][q] for coalesced access
__device__ float g_nd[NLISTS][NL][NPTS];
__device__ int   g_ni[NLISTS][NL][NPTS];

// ---- f32x2 packed helpers (sm_103a) ----
__device__ __forceinline__ ull pack2(float lo, float hi) {
    ull r; asm("mov.b64 %0, {%1,%2};" : "=l"(r) : "f"(lo), "f"(hi)); return r;
}
__device__ __forceinline__ float2 asf2(ull v) {
    float2 r; asm("mov.b64 {%0,%1}, %2;" : "=f"(r.x), "=f"(r.y) : "l"(v));
    return r;
}
__device__ __forceinline__ ull fma2(ull a, ull b, ull c) {
    ull d; asm("fma.rn.f32x2 %0, %1, %2, %3;" : "=l"(d) : "l"(a), "l"(b), "l"(c));
    return d;
}

__device__ __forceinline__ unsigned smem_u32(const void* p) {
    unsigned a;
    asm("{ .reg .u64 t; cvta.to.shared.u64 t, %1; cvt.u32.u64 %0, t; }"
        : "=r"(a) : "l"(p));
    return a;
}
__device__ __forceinline__ void sts_u8(unsigned addr, unsigned v) {
    asm volatile("st.shared.u8 [%0], %1;" :: "r"(addr), "r"(v) : "memory");
}

__device__ __forceinline__ unsigned minu(unsigned a, unsigned b) { return a < b ? a : b; }

__device__ __forceinline__ float warp_sum(float v) {
#pragma unroll
    for (int o = 16; o; o >>= 1) v += __shfl_xor_sync(0xffffffffu, v, o);
    return v;
}

// prep: build SoA + per-block partial sums of the three cheap losses (no atomics)
__global__ void prep_kernel(const float* __restrict__ pos,
                            const float* __restrict__ op,
                            const float* __restrict__ sc) {
    __shared__ float acc[3][8];
    int i = blockIdx.x * blockDim.x + threadIdx.x;   // 64 blocks x 256
    float x = pos[3 * i + 0], y = pos[3 * i + 1], z = pos[3 * i + 2];
    ((float*)g_sx)[i] = -2.0f * x;
    ((float*)g_sy)[i] = -2.0f * y;
    ((float*)g_sz)[i] = -2.0f * z;
    ((float*)g_sw)[i] = fmaf(z, z, fmaf(y, y, x * x));

    float o  = op[i];
    float sp = fabsf(o);
    float ol = (o - 0.5f) * (o - 0.5f);
    float sl = fabsf(sc[3 * i + 0] - 1.0f)
             + fabsf(sc[3 * i + 1] - 1.0f)
             + fabsf(sc[3 * i + 2] - 1.0f);
    sp = warp_sum(sp); ol = warp_sum(ol); sl = warp_sum(sl);
    int w = threadIdx.x >> 5;
    if ((threadIdx.x & 31) == 0) { acc[0][w] = sp; acc[1][w] = ol; acc[2][w] = sl; }
    __syncthreads();
    if (threadIdx.x == 0) {
        float a = 0, b = 0, c = 0;
#pragma unroll
        for (int k = 0; k < 8; k++) { a += acc[0][k]; b += acc[1][k]; c += acc[2][k]; }
        g_part[blockIdx.x] = make_float3(a, b, c);
    }
}

// branchless sorted insert: compares + select cascade (no inner branches)
__device__ __forceinline__ void insert_branchless(float d, int id,
                                                  float bd[NL], int bi[NL]) {
    bool lt[NL];
#pragma unroll
    for (int k = 0; k < NL; k++) lt[k] = d < bd[k];
#pragma unroll
    for (int k = NL - 1; k > 0; --k) {
        bd[k] = lt[k - 1] ? bd[k - 1] : (lt[k] ? d : bd[k]);
        bi[k] = lt[k - 1] ? bi[k - 1] : (lt[k] ? id : bi[k]);
    }
    bd[0] = lt[0] ? d : bd[0];
    bi[0] = lt[0] ? id : bi[0];
}

// value-only branchless sorted insert (for threshold merging)
__device__ __forceinline__ void insert_val(float d, float bd[NL]) {
    bool lt[NL];
#pragma unroll
    for (int k = 0; k < NL; k++) lt[k] = d < bd[k];
#pragma unroll
    for (int k = NL - 1; k > 0; --k)
        bd[k] = lt[k - 1] ? bd[k - 1] : (lt[k] ? d : bd[k]);
    bd[0] = lt[0] ? d : bd[0];
}

__device__ __forceinline__ float tscal(const float* fx, const float* fy,
                                       const float* fz, const float* fw, int c,
                                       float qx, float qy, float qz) {
    return fmaf(fx[c], qx, fmaf(fy[c], qy, fmaf(fz[c], qz, fw[c])));
}

// quad t-values (packed): min of the 4
__device__ __forceinline__ float quad_min(ulonglong2 X, ulonglong2 Y,
                                          ulonglong2 Z, ulonglong2 W,
                                          ull qx2, ull qy2, ull qz2) {
    ull t01 = fma2(X.x, qx2, fma2(Y.x, qy2, fma2(Z.x, qz2, W.x)));
    ull t23 = fma2(X.y, qx2, fma2(Y.y, qy2, fma2(Z.y, qz2, W.y)));
    float2 a = asf2(t01), b = asf2(t23);
    return fminf(fminf(a.x, a.y), fminf(b.x, b.y));
}

// Bootstrap: exact top-11 of one 512-candidate half per query (t-space).
// grid = (NPTS/QPB) * 2 = 256 blocks; block handles half = blockIdx & 1.
// S0 forced inserts, then two buffered rounds with running-pointer stores.
// Region is 100B/thread; max buffered quads in any round is 96 -> never overflows.
__global__ void __launch_bounds__(QPB) boot_kernel(const float* __restrict__ pos) {
    __shared__ ulonglong2 sx[BCH / 4], sy[BCH / 4], sz[BCH / 4], sw[BCH / 4]; // 8KB
    __shared__ unsigned char buf[QPB][BUFW];                                  // 12.5KB

    const int half = blockIdx.x & 1;
    const int q    = (blockIdx.x >> 1) * QPB + threadIdx.x;
    const int base = half * BCH;
    const float qx = pos[3 * q + 0], qy = pos[3 * q + 1], qz = pos[3 * q + 2];

    sx[threadIdx.x] = g_sx[base / 4 + threadIdx.x];
    sy[threadIdx.x] = g_sy[base / 4 + threadIdx.x];
    sz[threadIdx.x] = g_sz[base / 4 + threadIdx.x];
    sw[threadIdx.x] = g_sw[base / 4 + threadIdx.x];
    __syncthreads();

    const float* fx = (const float*)sx;
    const float* fy = (const float*)sy;
    const float* fz = (const float*)sz;
    const float* fw = (const float*)sw;

    float bd[NL]; int bi[NL];
#pragma unroll
    for (int k = 0; k < NL; k++) { bd[k] = CUDART_INF_F; bi[k] = -1; }

    // stage 0: unconditional insert of first S0 candidates
#pragma unroll 1
    for (int c = 0; c < S0; c++)
        insert_branchless(tscal(fx, fy, fz, fw, c, qx, qy, qz), c, bd, bi);

    const unsigned p0 = smem_u32(buf[threadIdx.x]);
    const ull qx2 = pack2(qx, qx), qy2 = pack2(qy, qy), qz2 = pack2(qz, qz);

    // round 1: c in [S0, 128) gated by 11th-of-32 (<=24 quads, fits region)
    {
        const float thr = bd[NL - 1];
        unsigned p = p0;
#pragma unroll 2
        for (int g = S0 / 4; g < 128 / 4; g++) {
            float m = quad_min(sx[g], sy[g], sz[g], sw[g], qx2, qy2, qz2);
            sts_u8(p, (unsigned)g);          // always-store; advances only on pass
            p += (m < thr);
        }
        int cnt = (int)(p - p0);
#pragma unroll 1
        for (int e = 0; e < cnt; e++) {
            int c4 = ((int)buf[threadIdx.x][e]) * 4;
#pragma unroll
            for (int u = 0; u < 4; u++) {
                float t = tscal(fx, fy, fz, fw, c4 + u, qx, qy, qz);
                if (t < bd[NL - 1]) insert_branchless(t, c4 + u, bd, bi);
            }
        }
    }

    // round 2: c in [128, BCH) gated by exact 11th-of-128 (<=96 quads, fits region)
    {
        const float thr = bd[NL - 1];
        unsigned p = p0;
#pragma unroll 2
        for (int g = 128 / 4; g < BCH / 4; g++) {
            float m = quad_min(sx[g], sy[g], sz[g], sw[g], qx2, qy2, qz2);
            sts_u8(p, (unsigned)g);
            p += (m < thr);
        }
        int cnt = (int)(p - p0);
#pragma unroll 1
        for (int e = 0; e < cnt; e++) {
            int c4 = ((int)buf[threadIdx.x][e]) * 4;
#pragma unroll
            for (int u = 0; u < 4; u++) {
                float t = tscal(fx, fy, fz, fw, c4 + u, qx, qy, qz);
                if (t < bd[NL - 1]) insert_branchless(t, c4 + u, bd, bi);
            }
        }
    }

#pragma unroll
    for (int k = 0; k < NL; k++) {
        g_nd[half][k][q] = bd[k];
        g_ni[half][k][q] = base + bi[k];   // bi is local; never -1 (S0 >= 11)
    }
}

// Threshold merge: exact 11th-of-1024 per query from the two boot half lists.
// Also zeroes the smoothness accumulator (runs before merge_kernel).
__global__ void thr_kernel() {
    int q = blockIdx.x * blockDim.x + threadIdx.x;
    if (q == 0) g_smooth = 0.0f;
    float bd[NL];
#pragma unroll
    for (int k = 0; k < NL; k++) bd[k] = g_nd[0][k][q];   // already sorted
#pragma unroll
    for (int k = 0; k < NL; k++) insert_val(g_nd[1][k][q], bd);
    g_thr[q] = bd[NL - 1];
}

// Phase B: 30 chunks of 512 over candidates [1024, NPTS), seeded by the exact
// 11th-of-1024 threshold (upper bound on global 11th -> exact).
// 2 queries/thread, packed-pair tile, running-pointer u8 quad buffers:
//   A-buffer at [0,34), B-buffer at [34,66), pad [66,100). A-overflow runs into
//   B (detected: cntA>32 -> rescan A and B); B is pointer-clamped into the pad
//   (cntB>32 -> rescan B). No silent-corruption path.
// grid = (NPTS/(2*QPB)) * NCHB = 1920 blocks of 128.
__global__ void __launch_bounds__(QPB) knnb_kernel(const float* __restrict__ pos) {
    __shared__ ulonglong2 sx[CHB / 4], sy[CHB / 4], sz[CHB / 4], sw[CHB / 4]; // 8KB
    __shared__ unsigned char buf[QPB][BUFW];                                  // 12.5KB

    const int l  = (int)(blockIdx.x % NCHB);
    const int qA = (int)(blockIdx.x / NCHB) * (2 * QPB) + threadIdx.x;
    const int qB = qA + QPB;

    const float qxA = pos[3 * qA + 0], qyA = pos[3 * qA + 1], qzA = pos[3 * qA + 2];
    const float qxB = pos[3 * qB + 0], qyB = pos[3 * qB + 1], qzB = pos[3 * qB + 2];

    const int base = 2 * BCH + l * CHB;
    sx[threadIdx.x] = g_sx[base / 4 + threadIdx.x];
    sy[threadIdx.x] = g_sy[base / 4 + threadIdx.x];
    sz[threadIdx.x] = g_sz[base / 4 + threadIdx.x];
    sw[threadIdx.x] = g_sw[base / 4 + threadIdx.x];
    __syncthreads();

    const float thrA = g_thr[qA];   // exact 11-of-1024 (coalesced)
    const float thrB = g_thr[qB];

    const ull qxA2 = pack2(qxA, qxA), qyA2 = pack2(qyA, qyA), qzA2 = pack2(qzA, qzA);
    const ull qxB2 = pack2(qxB, qxB), qyB2 = pack2(qyB, qyB), qzB2 = pack2(qzB, qzB);

    const unsigned p0 = smem_u32(buf[threadIdx.x]);
    unsigned pA = p0;
    unsigned pB = p0 + OFFB;
    const unsigned pBlim = p0 + BLIM;

#pragma unroll 4
    for (int g = 0; g < CHB / 4; g++) {
        ulonglong2 X = sx[g], Y = sy[g], Z = sz[g], W = sw[g];

        ull tA01 = fma2(X.x, qxA2, fma2(Y.x, qyA2, fma2(Z.x, qzA2, W.x)));
        ull tA23 = fma2(X.y, qxA2, fma2(Y.y, qyA2, fma2(Z.y, qzA2, W.y)));
        ull tB01 = fma2(X.x, qxB2, fma2(Y.x, qyB2, fma2(Z.x, qzB2, W.x)));
        ull tB23 = fma2(X.y, qxB2, fma2(Y.y, qyB2, fma2(Z.y, qzB2, W.y)));

        float2 a0 = asf2(tA01), a1 = asf2(tA23);
        float2 b0 = asf2(tB01), b1 = asf2(tB23);

        float mA = fminf(fminf(a0.x, a0.y), fminf(a1.x, a1.y));
        float mB = fminf(fminf(b0.x, b0.y), fminf(b1.x, b1.y));

        sts_u8(pA, (unsigned)g);
        pA += (mA < thrA);
        sts_u8(pB, (unsigned)g);
        pB += (mB < thrB);
        pB = minu(pB, pBlim);       // keeps B in its own pad on overflow
    }

    const int cntA = (int)(pA - p0);
    const int cntB = (int)(pB - (p0 + OFFB));
    const bool rsA = cntA > 32;             // A ran into B's region
    const bool rsB = rsA || (cntB > 32);    // B corrupted or clamped

    const float* fx = (const float*)sx;
    const float* fy = (const float*)sy;
    const float* fz = (const float*)sz;
    const float* fw = (const float*)sw;

    // ---- query A post-pass ----
    {
        float bd[NL]; int bi[NL];
#pragma unroll
        for (int k = 0; k < NL; k++) { bd[k] = thrA; bi[k] = -1; }
        if (rsA) {
#pragma unroll 1
            for (int c = 0; c < CHB; c++) {
                float t = tscal(fx, fy, fz, fw, c, qxA, qyA, qzA);
                if (t < bd[NL - 1]) insert_branchless(t, base + c, bd, bi);
            }
        } else {
#pragma unroll 1
            for (int e = 0; e < cntA; e++) {
                int c4 = ((int)buf[threadIdx.x][e]) * 4;
#pragma unroll
                for (int u = 0; u < 4; u++) {
                    float t = tscal(fx, fy, fz, fw, c4 + u, qxA, qyA, qzA);
                    if (t < bd[NL - 1]) insert_branchless(t, base + c4 + u, bd, bi);
                }
            }
        }
#pragma unroll
        for (int k = 0; k < NL; k++) {
            g_nd[2 + l][k][qA] = bd[k];
            g_ni[2 + l][k][qA] = bi[k];
        }
    }

    // ---- query B post-pass ----
    {
        float bd[NL]; int bi[NL];
#pragma unroll
        for (int k = 0; k < NL; k++) { bd[k] = thrB; bi[k] = -1; }
        if (rsB) {
#pragma unroll 1
            for (int c = 0; c < CHB; c++) {
                float t = tscal(fx, fy, fz, fw, c, qxB, qyB, qzB);
                if (t < bd[NL - 1]) insert_branchless(t, base + c, bd, bi);
            }
        } else {
#pragma unroll 1
            for (int e = 0; e < cntB; e++) {
                int c4 = ((int)buf[threadIdx.x][OFFB + e]) * 4;
#pragma unroll
                for (int u = 0; u < 4; u++) {
                    float t = tscal(fx, fy, fz, fw, c4 + u, qxB, qyB, qzB);
                    if (t < bd[NL - 1]) insert_branchless(t, base + c4 + u, bd, bi);
                }
            }
        }
#pragma unroll
        for (int k = 0; k < NL; k++) {
            g_nd[2 + l][k][qB] = bd[k];
            g_ni[2 + l][k][qB] = bi[k];
        }
    }
}

// merge all NLISTS lists per query (filtering self/invalid), accumulate smoothness
__global__ void merge_kernel(const float* __restrict__ op) {
    int q = blockIdx.x * blockDim.x + threadIdx.x;

    float bd[NL]; int bi[NL];
#pragma unroll
    for (int k = 0; k < NL; k++) { bd[k] = CUDART_INF_F; bi[k] = -1; }

#pragma unroll 1
    for (int c = 0; c < NLISTS; c++) {
        // hoisted loads: MLP=22 per list
        float dv[NL]; int jv[NL];
#pragma unroll
        for (int e = 0; e < NL; e++) {
            dv[e] = g_nd[c][e][q];   // coalesced across lanes
            jv[e] = g_ni[c][e][q];
        }
#pragma unroll
        for (int e = 0; e < NL; e++) {
            float d = dv[e];
            int   j = jv[e];
            if (j < 0 || j == q) d = CUDART_INF_F;   // invalid/self never inserts
            if (__ballot_sync(0xffffffffu, d < bd[NL - 1]))
                insert_branchless(d, j, bd, bi);
        }
    }

    float oq = op[q];
    float s = 0.0f;
#pragma unroll
    for (int k = 0; k < KNN; k++)
        s += fabsf(oq - op[bi[k]]);

    s = warp_sum(s);
    if ((threadIdx.x & 31) == 0) atomicAdd(&g_smooth, s);
}

__global__ void final_kernel(float* __restrict__ out) {
    int t = threadIdx.x;   // 32 threads
    float3 p1 = g_part[t], p2 = g_part[t + 32];
    float sp = warp_sum(p1.x + p2.x);
    float ol = warp_sum(p1.y + p2.y);
    float sl = warp_sum(p1.z + p2.z);
    if (t == 0) {
        float sparsity = sp * (1.0f / NPTS);
        float opacity  = ol * (1.0f / NPTS);
        float scale    = sl * (1.0f / (3.0f * NPTS));
        float smooth   = g_smooth * (1.0f / ((float)NPTS * KNN));
        out[0] = 0.01f * sparsity + 0.1f * smooth + scale + opacity;
    }
}

extern "C" void kernel_launch(void* const* d_in, const int* in_sizes, int n_in,
                              void* d_out, int out_size) {
    const float* pos = (const float*)d_in[0];
    const float* op  = (const float*)d_in[1];
    const float* sc  = (const float*)d_in[2];
    float* out = (float*)d_out;

    prep_kernel<<<NPTS / 256, 256>>>(pos, op, sc);
    boot_kernel<<<(NPTS / QPB) * 2, QPB>>>(pos);
    thr_kernel<<<NPTS / 256, 256>>>();
    knnb_kernel<<<(NPTS / (2 * QPB)) * NCHB, QPB>>>(pos);
    merge_kernel<<<NPTS / 128, 128>>>(op);
    final_kernel<<<1, 32>>>(out);
}